// round 1
// baseline (speedup 1.0000x reference)
#include <cuda_runtime.h>
#include <math.h>

// ---------------- problem constants ----------------
// x: (2, 48, 96, 14, 192), windows (2,6,2) -> 24 tokens, 5376 windows
#define NTOK_TOTAL 129024   // 5376 * 24
#define NWIN       5376
#define CDIM       192
#define HEADS      6
#define DHEAD      32
#define HID        768

// ---------------- scratch (device globals; allocation-free) ----------------
__device__ float g_xw  [(size_t)NTOK_TOTAL * 192];  // gathered shortcut
__device__ float g_h   [(size_t)NTOK_TOTAL * 192];  // LN1 / LN2 output
__device__ float g_qkv [(size_t)NTOK_TOTAL * 576];
__device__ float g_attn[(size_t)NTOK_TOTAL * 192];
__device__ float g_x2  [(size_t)NTOK_TOTAL * 192];  // shortcut + proj
__device__ float g_hid [(size_t)NTOK_TOTAL * 768];

// token index -> offset of its row in the (B,H,W,D,C) tensor (also used for scatter)
__device__ __forceinline__ size_t token_src_offset(int t) {
    int wi = t / 24, n = t % 24;
    int i3 = n / 12, j3 = (n >> 1) % 6, k3 = n & 1;
    int d0 = wi % 7;  int r = wi / 7;
    int w0 = r % 16;  r /= 16;
    int h0 = r % 24;  int b0 = r / 24;
    return ((((size_t)b0 * 48 + (h0 * 2 + i3)) * 96 + (w0 * 6 + j3)) * 14
            + (d0 * 2 + k3)) * 192;
}

__device__ __forceinline__ float warp_sum(float v) {
#pragma unroll
    for (int o = 16; o; o >>= 1) v += __shfl_xor_sync(0xffffffffu, v, o);
    return v;
}
__device__ __forceinline__ float warp_max(float v) {
#pragma unroll
    for (int o = 16; o; o >>= 1) v = fmaxf(v, __shfl_xor_sync(0xffffffffu, v, o));
    return v;
}

// ---------------- kernel 1: gather windows + LayerNorm1 ----------------
// 8 warps/block, 1 warp per token. Writes g_xw (raw) and g_h (normalized).
__global__ __launch_bounds__(256) void gather_ln1_kernel(
    const float* __restrict__ x, const float* __restrict__ gam,
    const float* __restrict__ bet)
{
    int t    = blockIdx.x * 8 + (threadIdx.x >> 5);
    int lane = threadIdx.x & 31;
    size_t src = token_src_offset(t);

    float v[6];
    float s = 0.f;
#pragma unroll
    for (int q = 0; q < 6; q++) { v[q] = x[src + lane + q * 32]; s += v[q]; }
    float mean = warp_sum(s) * (1.0f / 192.0f);
    float vs = 0.f;
#pragma unroll
    for (int q = 0; q < 6; q++) { float d = v[q] - mean; vs += d * d; }
    float var = warp_sum(vs) * (1.0f / 192.0f);
    float rstd = rsqrtf(var + 1e-5f);

    size_t dst = (size_t)t * 192;
#pragma unroll
    for (int q = 0; q < 6; q++) {
        int c = lane + q * 32;
        g_xw[dst + c] = v[q];
        g_h [dst + c] = (v[q] - mean) * rstd * gam[c] + bet[c];
    }
}

// ---------------- kernel: LayerNorm2 (linear in/out) ----------------
__global__ __launch_bounds__(256) void ln2_kernel(
    const float* __restrict__ gam, const float* __restrict__ bet)
{
    int t    = blockIdx.x * 8 + (threadIdx.x >> 5);
    int lane = threadIdx.x & 31;
    size_t base = (size_t)t * 192;

    float v[6];
    float s = 0.f;
#pragma unroll
    for (int q = 0; q < 6; q++) { v[q] = g_x2[base + lane + q * 32]; s += v[q]; }
    float mean = warp_sum(s) * (1.0f / 192.0f);
    float vs = 0.f;
#pragma unroll
    for (int q = 0; q < 6; q++) { float d = v[q] - mean; vs += d * d; }
    float var = warp_sum(vs) * (1.0f / 192.0f);
    float rstd = rsqrtf(var + 1e-5f);
#pragma unroll
    for (int q = 0; q < 6; q++) {
        int c = lane + q * 32;
        g_h[base + c] = (v[q] - mean) * rstd * gam[c] + bet[c];
    }
}

// ---------------- SGEMM: C[M,N] = A[M,K] @ B[K,N] + epilogue ----------------
// BM=128, BN=64, BK=16, 256 threads, 8x4 register tile.
// EPI: 0 = +bias, 1 = +bias,gelu, 2 = +bias,+res (N==192), 3 = +bias,+res,scatter (N==192)
template <int EPI>
__global__ __launch_bounds__(256) void sgemm_kernel(
    const float* __restrict__ A, const float* __restrict__ B,
    const float* __restrict__ bias, const float* __restrict__ res,
    float* __restrict__ Cc, int N, int K)
{
    constexpr int BM = 128, BN = 64, BK = 16, TM = 8, TN = 4;
    __shared__ float As[BK][BM];
    __shared__ float Bs[BK][BN];

    const int tid  = threadIdx.x;
    const int row0 = blockIdx.x * BM;
    const int col0 = blockIdx.y * BN;
    const int tx = tid & 15, ty = tid >> 4;

    float acc[TM][TN];
#pragma unroll
    for (int i = 0; i < TM; i++)
#pragma unroll
        for (int j = 0; j < TN; j++) acc[i][j] = 0.f;

    const int aRow = tid >> 2, aK = (tid & 3) * 4;
    const int bK = tid >> 4, bN = (tid & 15) * 4;

    for (int kt = 0; kt < K; kt += BK) {
#pragma unroll
        for (int r = 0; r < 2; r++) {
            int m = aRow + r * 64;
            float4 a4 = *(const float4*)(A + (size_t)(row0 + m) * K + kt + aK);
            As[aK + 0][m] = a4.x; As[aK + 1][m] = a4.y;
            As[aK + 2][m] = a4.z; As[aK + 3][m] = a4.w;
        }
        float4 b4 = *(const float4*)(B + (size_t)(kt + bK) * N + col0 + bN);
        *(float4*)&Bs[bK][bN] = b4;
        __syncthreads();

#pragma unroll
        for (int k = 0; k < BK; k++) {
            float af[TM], bf[TN];
            *(float4*)&af[0] = *(const float4*)&As[k][ty * TM];
            *(float4*)&af[4] = *(const float4*)&As[k][ty * TM + 4];
            *(float4*)&bf[0] = *(const float4*)&Bs[k][tx * TN];
#pragma unroll
            for (int i = 0; i < TM; i++)
#pragma unroll
                for (int j = 0; j < TN; j++) acc[i][j] = fmaf(af[i], bf[j], acc[i][j]);
        }
        __syncthreads();
    }

    float4 bv = *(const float4*)(bias + col0 + tx * TN);
#pragma unroll
    for (int i = 0; i < TM; i++) {
        int row = row0 + ty * TM + i;
        float o0 = acc[i][0] + bv.x, o1 = acc[i][1] + bv.y;
        float o2 = acc[i][2] + bv.z, o3 = acc[i][3] + bv.w;
        if (EPI == 1) {
            o0 = 0.5f * o0 * (1.0f + erff(o0 * 0.70710678118654752f));
            o1 = 0.5f * o1 * (1.0f + erff(o1 * 0.70710678118654752f));
            o2 = 0.5f * o2 * (1.0f + erff(o2 * 0.70710678118654752f));
            o3 = 0.5f * o3 * (1.0f + erff(o3 * 0.70710678118654752f));
        }
        if (EPI == 2 || EPI == 3) {
            float4 r4 = *(const float4*)(res + (size_t)row * 192 + col0 + tx * TN);
            o0 += r4.x; o1 += r4.y; o2 += r4.z; o3 += r4.w;
        }
        size_t off;
        if (EPI == 3) off = token_src_offset(row) + col0 + tx * TN;
        else          off = (size_t)row * N + col0 + tx * TN;
        *(float4*)(Cc + off) = make_float4(o0, o1, o2, o3);
    }
}

// ---------------- attention: one block per window, one warp per head --------
__global__ __launch_bounds__(192) void attn_kernel(
    const float* __restrict__ bias_table, const int* __restrict__ rel_index)
{
    __shared__ float q_s[HEADS][24][32];   // later reused for P[24][24]
    __shared__ float v_s[HEADS][24][33];   // padded for column reads
    __shared__ int   rel_s[576];

    const int wi = blockIdx.x;
    const int h = threadIdx.x >> 5, lane = threadIdx.x & 31;
    const float* base = g_qkv + (size_t)wi * 24 * 576;

    for (int idx = threadIdx.x; idx < 576; idx += 192) rel_s[idx] = rel_index[idx];

    // coalesced q/v loads into smem (each warp its own head)
#pragma unroll
    for (int n = 0; n < 24; n++) {
        q_s[h][n][lane] = base[n * 576 +        h * 32 + lane];
        v_s[h][n][lane] = base[n * 576 + 384 +  h * 32 + lane];
    }
    __syncthreads();   // rel_s is cross-warp

    // k row m in registers (lane m)
    float kr[32];
    if (lane < 24) {
        const float* kp = base + lane * 576 + 192 + h * 32;
#pragma unroll
        for (int d = 0; d < 32; d += 4) {
            float4 k4 = *(const float4*)(kp + d);
            kr[d] = k4.x; kr[d + 1] = k4.y; kr[d + 2] = k4.z; kr[d + 3] = k4.w;
        }
    }

    const float scale = 0.17677669529663687f;  // 32^-0.5
    float s[24];
    if (lane < 24) {
#pragma unroll 4
        for (int n = 0; n < 24; n++) {
            float a = 0.f;
#pragma unroll
            for (int d = 0; d < 32; d += 4) {
                float4 q4 = *(const float4*)&q_s[h][n][d];
                a = fmaf(q4.x, kr[d], a);
                a = fmaf(q4.y, kr[d + 1], a);
                a = fmaf(q4.z, kr[d + 2], a);
                a = fmaf(q4.w, kr[d + 3], a);
            }
            s[n] = a * scale + bias_table[rel_s[n * 24 + lane] * HEADS + h];
        }
    } else {
#pragma unroll
        for (int n = 0; n < 24; n++) s[n] = -1e30f;
    }
    __syncwarp();

    // softmax over m (lanes), write P into q_s[h] (q no longer needed)
#pragma unroll 4
    for (int n = 0; n < 24; n++) {
        float mx = warp_max(s[n]);
        float e  = (lane < 24) ? __expf(s[n] - mx) : 0.f;
        float sm = warp_sum(e);
        if (lane < 24) q_s[h][n][lane] = e / sm;
    }
    __syncwarp();

    // out[n][d] = sum_m P[n][m] * v[m][d]   (lane = d)
    float vcol[24];
#pragma unroll
    for (int m = 0; m < 24; m++) vcol[m] = v_s[h][m][lane];

    float* ob = g_attn + (size_t)wi * 24 * 192 + h * 32 + lane;
#pragma unroll 4
    for (int n = 0; n < 24; n++) {
        float a = 0.f;
#pragma unroll
        for (int m4 = 0; m4 < 24; m4 += 4) {
            float4 p4 = *(const float4*)&q_s[h][n][m4];
            a = fmaf(p4.x, vcol[m4], a);
            a = fmaf(p4.y, vcol[m4 + 1], a);
            a = fmaf(p4.z, vcol[m4 + 2], a);
            a = fmaf(p4.w, vcol[m4 + 3], a);
        }
        ob[n * 192] = a;
    }
}

// ---------------- host launcher ----------------
extern "C" void kernel_launch(void* const* d_in, const int* in_sizes, int n_in,
                              void* d_out, int out_size)
{
    const float* x        = (const float*)d_in[0];
    const float* ln1_g    = (const float*)d_in[1];
    const float* ln1_b    = (const float*)d_in[2];
    const float* qkv_w    = (const float*)d_in[3];
    const float* qkv_b    = (const float*)d_in[4];
    const float* btab     = (const float*)d_in[5];
    const float* proj_w   = (const float*)d_in[6];
    const float* proj_b   = (const float*)d_in[7];
    const float* ln2_g    = (const float*)d_in[8];
    const float* ln2_b    = (const float*)d_in[9];
    const float* mlp_w1   = (const float*)d_in[10];
    const float* mlp_b1   = (const float*)d_in[11];
    const float* mlp_w2   = (const float*)d_in[12];
    const float* mlp_b2   = (const float*)d_in[13];
    const int*   rel_idx  = (const int*)d_in[14];
    float*       out      = (float*)d_out;

    float *p_h, *p_qkv, *p_attn, *p_x2, *p_hid, *p_xw;
    cudaGetSymbolAddress((void**)&p_xw,   g_xw);
    cudaGetSymbolAddress((void**)&p_h,    g_h);
    cudaGetSymbolAddress((void**)&p_qkv,  g_qkv);
    cudaGetSymbolAddress((void**)&p_attn, g_attn);
    cudaGetSymbolAddress((void**)&p_x2,   g_x2);
    cudaGetSymbolAddress((void**)&p_hid,  g_hid);

    const int Mb = NTOK_TOTAL / 128;  // 1008

    // 1. gather + LN1
    gather_ln1_kernel<<<NTOK_TOTAL / 8, 256>>>(x, ln1_g, ln1_b);
    // 2. QKV GEMM: [T,192] @ [192,576]
    sgemm_kernel<0><<<dim3(Mb, 576 / 64), 256>>>(p_h, qkv_w, qkv_b, nullptr, p_qkv, 576, 192);
    // 3. windowed attention
    attn_kernel<<<NWIN, 192>>>(btab, rel_idx);
    // 4. proj + residual: g_x2 = g_xw + attn @ proj_w + proj_b
    sgemm_kernel<2><<<dim3(Mb, 192 / 64), 256>>>(p_attn, proj_w, proj_b, p_xw, p_x2, 192, 192);
    // 5. LN2
    ln2_kernel<<<NTOK_TOTAL / 8, 256>>>(ln2_g, ln2_b);
    // 6. MLP1 + gelu: [T,192] @ [192,768]
    sgemm_kernel<1><<<dim3(Mb, 768 / 64), 256>>>(p_h, mlp_w1, mlp_b1, nullptr, p_hid, 768, 192);
    // 7. MLP2 + residual + scatter to output layout
    sgemm_kernel<3><<<dim3(Mb, 192 / 64), 256>>>(p_hid, mlp_w2, mlp_b2, p_x2, out, 192, 768);
}

// round 3
// speedup vs baseline: 1.9460x; 1.9460x over previous
#include <cuda_runtime.h>
#include <math.h>
#include <stdint.h>

// ---------------- problem constants ----------------
#define NTOK_TOTAL 129024   // 5376 windows * 24 tokens
#define NWIN       5376
#define HEADS      6

// ---------------- scratch (device globals) ----------------
__device__ float g_xw  [(size_t)NTOK_TOTAL * 192];
__device__ float g_h   [(size_t)NTOK_TOTAL * 192];
__device__ float g_qkv [(size_t)NTOK_TOTAL * 576];
__device__ float g_attn[(size_t)NTOK_TOTAL * 192];
__device__ float g_x2  [(size_t)NTOK_TOTAL * 192];
__device__ float g_hid [(size_t)NTOK_TOTAL * 768];
// pre-transposed weights (K-major: Wt[N][K])
__device__ float g_qkv_wt [576 * 192];
__device__ float g_proj_wt[192 * 192];
__device__ float g_w1t    [768 * 192];
__device__ float g_w2t    [192 * 768];

// ---------------- helpers ----------------
__device__ __forceinline__ size_t token_src_offset(int t) {
    int wi = t / 24, n = t % 24;
    int i3 = n / 12, j3 = (n >> 1) % 6, k3 = n & 1;
    int d0 = wi % 7;  int r = wi / 7;
    int w0 = r % 16;  r /= 16;
    int h0 = r % 24;  int b0 = r / 24;
    return ((((size_t)b0 * 48 + (h0 * 2 + i3)) * 96 + (w0 * 6 + j3)) * 14
            + (d0 * 2 + k3)) * 192;
}
__device__ __forceinline__ float warp_sum(float v) {
#pragma unroll
    for (int o = 16; o; o >>= 1) v += __shfl_xor_sync(0xffffffffu, v, o);
    return v;
}
__device__ __forceinline__ float warp_max(float v) {
#pragma unroll
    for (int o = 16; o; o >>= 1) v = fmaxf(v, __shfl_xor_sync(0xffffffffu, v, o));
    return v;
}
__device__ __forceinline__ uint32_t f2tf32(float f) {
    uint32_t u;
    asm("cvt.rna.tf32.f32 %0, %1;" : "=r"(u) : "f"(f));
    return u;
}
__device__ __forceinline__ void mma_tf32(float* d, const uint32_t* a,
                                         const uint32_t* b, const float* c) {
    asm volatile(
        "mma.sync.aligned.m16n8k8.row.col.f32.tf32.tf32.f32 "
        "{%0,%1,%2,%3}, {%4,%5,%6,%7}, {%8,%9}, {%10,%11,%12,%13};"
        : "=f"(d[0]), "=f"(d[1]), "=f"(d[2]), "=f"(d[3])
        : "r"(a[0]), "r"(a[1]), "r"(a[2]), "r"(a[3]),
          "r"(b[0]), "r"(b[1]),
          "f"(c[0]), "f"(c[1]), "f"(c[2]), "f"(c[3]));
}

// ---------------- weight transpose [K,N] -> [N,K] ----------------
__global__ void transpose_kernel(const float* __restrict__ W, float* __restrict__ Wt,
                                 int K, int N) {
    __shared__ float t[32][33];
    int kb = blockIdx.x * 32, nb = blockIdx.y * 32;
    int x = threadIdx.x, y = threadIdx.y;
#pragma unroll
    for (int j = 0; j < 32; j += 8) t[y + j][x] = W[(size_t)(kb + y + j) * N + nb + x];
    __syncthreads();
#pragma unroll
    for (int j = 0; j < 32; j += 8) Wt[(size_t)(nb + y + j) * K + kb + x] = t[x][y + j];
}

// ---------------- gather + LN1 ----------------
__global__ __launch_bounds__(256) void gather_ln1_kernel(
    const float* __restrict__ x, const float* __restrict__ gam, const float* __restrict__ bet)
{
    int t = blockIdx.x * 8 + (threadIdx.x >> 5);
    int lane = threadIdx.x & 31;
    size_t src = token_src_offset(t);
    float v[6]; float s = 0.f;
#pragma unroll
    for (int q = 0; q < 6; q++) { v[q] = x[src + lane + q * 32]; s += v[q]; }
    float mean = warp_sum(s) * (1.0f / 192.0f);
    float vs = 0.f;
#pragma unroll
    for (int q = 0; q < 6; q++) { float d = v[q] - mean; vs += d * d; }
    float rstd = rsqrtf(warp_sum(vs) * (1.0f / 192.0f) + 1e-5f);
    size_t dst = (size_t)t * 192;
#pragma unroll
    for (int q = 0; q < 6; q++) {
        int c = lane + q * 32;
        g_xw[dst + c] = v[q];
        g_h [dst + c] = (v[q] - mean) * rstd * gam[c] + bet[c];
    }
}

// ---------------- LN2 ----------------
__global__ __launch_bounds__(256) void ln2_kernel(
    const float* __restrict__ gam, const float* __restrict__ bet)
{
    int t = blockIdx.x * 8 + (threadIdx.x >> 5);
    int lane = threadIdx.x & 31;
    size_t base = (size_t)t * 192;
    float v[6]; float s = 0.f;
#pragma unroll
    for (int q = 0; q < 6; q++) { v[q] = g_x2[base + lane + q * 32]; s += v[q]; }
    float mean = warp_sum(s) * (1.0f / 192.0f);
    float vs = 0.f;
#pragma unroll
    for (int q = 0; q < 6; q++) { float d = v[q] - mean; vs += d * d; }
    float rstd = rsqrtf(warp_sum(vs) * (1.0f / 192.0f) + 1e-5f);
#pragma unroll
    for (int q = 0; q < 6; q++) {
        int c = lane + q * 32;
        g_h[base + c] = (v[q] - mean) * rstd * gam[c] + bet[c];
    }
}

// ---------------- attention (per-window, fp32) ----------------
__global__ __launch_bounds__(192) void attn_kernel(
    const float* __restrict__ bias_table, const int* __restrict__ rel_index)
{
    __shared__ float q_s[HEADS][24][32];
    __shared__ float v_s[HEADS][24][33];
    __shared__ int   rel_s[576];
    const int wi = blockIdx.x;
    const int h = threadIdx.x >> 5, lane = threadIdx.x & 31;
    const float* base = g_qkv + (size_t)wi * 24 * 576;
    for (int idx = threadIdx.x; idx < 576; idx += 192) rel_s[idx] = rel_index[idx];
#pragma unroll
    for (int n = 0; n < 24; n++) {
        q_s[h][n][lane] = base[n * 576 +       h * 32 + lane];
        v_s[h][n][lane] = base[n * 576 + 384 + h * 32 + lane];
    }
    __syncthreads();
    float kr[32];
    if (lane < 24) {
        const float* kp = base + lane * 576 + 192 + h * 32;
#pragma unroll
        for (int d = 0; d < 32; d += 4) {
            float4 k4 = *(const float4*)(kp + d);
            kr[d] = k4.x; kr[d+1] = k4.y; kr[d+2] = k4.z; kr[d+3] = k4.w;
        }
    }
    const float scale = 0.17677669529663687f;
    float s[24];
    if (lane < 24) {
#pragma unroll 4
        for (int n = 0; n < 24; n++) {
            float a = 0.f;
#pragma unroll
            for (int d = 0; d < 32; d += 4) {
                float4 q4 = *(const float4*)&q_s[h][n][d];
                a = fmaf(q4.x, kr[d], a); a = fmaf(q4.y, kr[d+1], a);
                a = fmaf(q4.z, kr[d+2], a); a = fmaf(q4.w, kr[d+3], a);
            }
            s[n] = a * scale + bias_table[rel_s[n * 24 + lane] * HEADS + h];
        }
    } else {
#pragma unroll
        for (int n = 0; n < 24; n++) s[n] = -1e30f;
    }
    __syncwarp();
#pragma unroll 4
    for (int n = 0; n < 24; n++) {
        float mx = warp_max(s[n]);
        float e = (lane < 24) ? __expf(s[n] - mx) : 0.f;
        float sm = warp_sum(e);
        if (lane < 24) q_s[h][n][lane] = e / sm;
    }
    __syncwarp();
    float vcol[24];
#pragma unroll
    for (int m = 0; m < 24; m++) vcol[m] = v_s[h][m][lane];
    float* ob = g_attn + (size_t)wi * 24 * 192 + h * 32 + lane;
#pragma unroll 4
    for (int n = 0; n < 24; n++) {
        float a = 0.f;
#pragma unroll
        for (int m4 = 0; m4 < 24; m4 += 4) {
            float4 p4 = *(const float4*)&q_s[h][n][m4];
            a = fmaf(p4.x, vcol[m4], a); a = fmaf(p4.y, vcol[m4+1], a);
            a = fmaf(p4.z, vcol[m4+2], a); a = fmaf(p4.w, vcol[m4+3], a);
        }
        ob[n * 192] = a;
    }
}

// ---------------- TF32 tensor GEMM: C[M,N] = A[M,K] @ Bt[N,K]^T + epi ------
// BM=128, BN=96, BK=32, 8 warps (4 x 2), warp tile 32x48 = 2x6 m16n8k8.
// Smem stride 36 (== 4 mod 32) -> conflict-free fragment LDS.
// EPI: 0 bias, 1 bias+gelu, 2 bias+res, 3 bias+res+scatter
template <int EPI>
__global__ __launch_bounds__(256) void tc_gemm(
    const float* __restrict__ A, const float* __restrict__ Bt,
    const float* __restrict__ bias, const float* __restrict__ res,
    float* __restrict__ Cc, int N, int K)
{
    constexpr int BK = 32, LDS_ = 36;
    __shared__ uint32_t As[128 * LDS_];
    __shared__ uint32_t Bs[96 * LDS_];

    const int tid  = threadIdx.x;
    const int lane = tid & 31;
    const int wid  = tid >> 5;
    const int wm   = wid & 3;          // warp row (0..3) -> 32 rows each
    const int wn   = wid >> 2;         // warp col (0..1) -> 48 cols each
    const int row0 = blockIdx.x * 128;
    const int col0 = blockIdx.y * 96;

    const int gq   = lane >> 2;        // groupID (0..7)
    const int tg   = lane & 3;         // thread-in-group (0..3)

    float acc[2][6][4];
#pragma unroll
    for (int mi = 0; mi < 2; mi++)
#pragma unroll
        for (int ni = 0; ni < 6; ni++)
#pragma unroll
            for (int j = 0; j < 4; j++) acc[mi][ni][j] = 0.f;

    // global load mapping: A 16 floats/thread, B 12 floats/thread
    float4 pa[4], pb[3];
    const int nstages = K / BK;

    auto load_stage = [&](int s) {
        const float* Ag = A + (size_t)row0 * K + s * BK;
        const float* Bg = Bt + (size_t)col0 * K + s * BK;
#pragma unroll
        for (int j = 0; j < 4; j++) {
            int idx = tid + j * 256;
            int r = idx >> 3, c4 = idx & 7;
            pa[j] = *(const float4*)(Ag + (size_t)r * K + c4 * 4);
        }
#pragma unroll
        for (int j = 0; j < 3; j++) {
            int idx = tid + j * 256;
            int r = idx >> 3, c4 = idx & 7;
            pb[j] = *(const float4*)(Bg + (size_t)r * K + c4 * 4);
        }
    };
    auto store_stage = [&]() {
#pragma unroll
        for (int j = 0; j < 4; j++) {
            int idx = tid + j * 256;
            int r = idx >> 3, c4 = idx & 7;
            uint4 u = make_uint4(f2tf32(pa[j].x), f2tf32(pa[j].y),
                                 f2tf32(pa[j].z), f2tf32(pa[j].w));
            *(uint4*)&As[r * LDS_ + c4 * 4] = u;
        }
#pragma unroll
        for (int j = 0; j < 3; j++) {
            int idx = tid + j * 256;
            int r = idx >> 3, c4 = idx & 7;
            uint4 u = make_uint4(f2tf32(pb[j].x), f2tf32(pb[j].y),
                                 f2tf32(pb[j].z), f2tf32(pb[j].w));
            *(uint4*)&Bs[r * LDS_ + c4 * 4] = u;
        }
    };

    load_stage(0);
    store_stage();
    __syncthreads();

    for (int s = 0; s < nstages; s++) {
        if (s + 1 < nstages) load_stage(s + 1);

#pragma unroll
        for (int kk = 0; kk < BK; kk += 8) {
            uint32_t bfr[6][2];
#pragma unroll
            for (int ni = 0; ni < 6; ni++) {
                int cb = (wn * 48 + ni * 8 + gq) * LDS_ + kk + tg;
                bfr[ni][0] = Bs[cb];
                bfr[ni][1] = Bs[cb + 4];
            }
#pragma unroll
            for (int mi = 0; mi < 2; mi++) {
                int rb = (wm * 32 + mi * 16 + gq) * LDS_ + kk + tg;
                uint32_t afr[4];
                afr[0] = As[rb];
                afr[1] = As[rb + 8 * LDS_];
                afr[2] = As[rb + 4];
                afr[3] = As[rb + 8 * LDS_ + 4];
#pragma unroll
                for (int ni = 0; ni < 6; ni++)
                    mma_tf32(acc[mi][ni], afr, bfr[ni], acc[mi][ni]);
            }
        }
        __syncthreads();
        if (s + 1 < nstages) {
            store_stage();
            __syncthreads();
        }
    }

    // ---- epilogue ----
#pragma unroll
    for (int mi = 0; mi < 2; mi++) {
#pragma unroll
        for (int ni = 0; ni < 6; ni++) {
            int row = row0 + wm * 32 + mi * 16 + gq;
            int col = col0 + wn * 48 + ni * 8 + tg * 2;
            float b0 = bias[col], b1 = bias[col + 1];
#pragma unroll
            for (int hh = 0; hh < 2; hh++) {
                int r = row + hh * 8;
                float v0 = acc[mi][ni][hh * 2]     + b0;
                float v1 = acc[mi][ni][hh * 2 + 1] + b1;
                if (EPI == 1) {
                    v0 = 0.5f * v0 * (1.0f + erff(v0 * 0.70710678118654752f));
                    v1 = 0.5f * v1 * (1.0f + erff(v1 * 0.70710678118654752f));
                }
                if (EPI >= 2) {
                    const float* rp = res + (size_t)r * 192 + col;
                    v0 += rp[0]; v1 += rp[1];
                }
                size_t off;
                if (EPI == 3) off = token_src_offset(r) + col;
                else          off = (size_t)r * N + col;
                *(float2*)(Cc + off) = make_float2(v0, v1);
            }
        }
    }
}

// ---------------- host launcher ----------------
extern "C" void kernel_launch(void* const* d_in, const int* in_sizes, int n_in,
                              void* d_out, int out_size)
{
    const float* x      = (const float*)d_in[0];
    const float* ln1_g  = (const float*)d_in[1];
    const float* ln1_b  = (const float*)d_in[2];
    const float* qkv_w  = (const float*)d_in[3];
    const float* qkv_b  = (const float*)d_in[4];
    const float* btab   = (const float*)d_in[5];
    const float* proj_w = (const float*)d_in[6];
    const float* proj_b = (const float*)d_in[7];
    const float* ln2_g  = (const float*)d_in[8];
    const float* ln2_b  = (const float*)d_in[9];
    const float* mlp_w1 = (const float*)d_in[10];
    const float* mlp_b1 = (const float*)d_in[11];
    const float* mlp_w2 = (const float*)d_in[12];
    const float* mlp_b2 = (const float*)d_in[13];
    const int*   rel_idx= (const int*)d_in[14];
    float*       out    = (float*)d_out;

    float *p_h, *p_qkv, *p_attn, *p_x2, *p_hid, *p_xw;
    float *p_qkv_wt, *p_proj_wt, *p_w1t, *p_w2t;
    cudaGetSymbolAddress((void**)&p_xw,   g_xw);
    cudaGetSymbolAddress((void**)&p_h,    g_h);
    cudaGetSymbolAddress((void**)&p_qkv,  g_qkv);
    cudaGetSymbolAddress((void**)&p_attn, g_attn);
    cudaGetSymbolAddress((void**)&p_x2,   g_x2);
    cudaGetSymbolAddress((void**)&p_hid,  g_hid);
    cudaGetSymbolAddress((void**)&p_qkv_wt,  g_qkv_wt);
    cudaGetSymbolAddress((void**)&p_proj_wt, g_proj_wt);
    cudaGetSymbolAddress((void**)&p_w1t,  g_w1t);
    cudaGetSymbolAddress((void**)&p_w2t,  g_w2t);

    dim3 tb(32, 8);
    transpose_kernel<<<dim3(6, 18), tb>>>(qkv_w,  p_qkv_wt,  192, 576);
    transpose_kernel<<<dim3(6, 6),  tb>>>(proj_w, p_proj_wt, 192, 192);
    transpose_kernel<<<dim3(6, 24), tb>>>(mlp_w1, p_w1t,     192, 768);
    transpose_kernel<<<dim3(24, 6), tb>>>(mlp_w2, p_w2t,     768, 192);

    gather_ln1_kernel<<<NTOK_TOTAL / 8, 256>>>(x, ln1_g, ln1_b);

    const int Mb = NTOK_TOTAL / 128;  // 1008
    // QKV: [T,192] @ [192,576]
    tc_gemm<0><<<dim3(Mb, 6), 256>>>(p_h, p_qkv_wt, qkv_b, nullptr, p_qkv, 576, 192);
    // attention
    attn_kernel<<<NWIN, 192>>>(btab, rel_idx);
    // proj + residual
    tc_gemm<2><<<dim3(Mb, 2), 256>>>(p_attn, p_proj_wt, proj_b, p_xw, p_x2, 192, 192);
    // LN2
    ln2_kernel<<<NTOK_TOTAL / 8, 256>>>(ln2_g, ln2_b);
    // MLP1 + gelu
    tc_gemm<1><<<dim3(Mb, 8), 256>>>(p_h, p_w1t, mlp_b1, nullptr, p_hid, 768, 192);
    // MLP2 + residual + scatter
    tc_gemm<3><<<dim3(Mb, 2), 256>>>(p_hid, p_w2t, mlp_b2, p_x2, out, 192, 768);
}

// round 4
// speedup vs baseline: 3.1175x; 1.6020x over previous
#include <cuda_runtime.h>
#include <cuda_bf16.h>
#include <math.h>
#include <stdint.h>

typedef __nv_bfloat16 bf16;

// ---------------- problem constants ----------------
#define NTOK_TOTAL 129024   // 5376 windows * 24 tokens
#define NWIN       5376
#define HEADS      6

// ---------------- scratch (device globals) ----------------
__device__ float g_xw  [(size_t)NTOK_TOTAL * 192];   // residual trunk (fp32)
__device__ float g_x2  [(size_t)NTOK_TOTAL * 192];   // trunk after proj (fp32)
__device__ bf16  g_h   [(size_t)NTOK_TOTAL * 192];   // LN out (bf16, GEMM A)
__device__ bf16  g_qkv [(size_t)NTOK_TOTAL * 576];
__device__ bf16  g_attn[(size_t)NTOK_TOTAL * 192];
__device__ bf16  g_hid [(size_t)NTOK_TOTAL * 768];
// pre-transposed bf16 weights (K-major: Wt[N][K])
__device__ bf16 g_qkv_wt [576 * 192];
__device__ bf16 g_proj_wt[192 * 192];
__device__ bf16 g_w1t    [768 * 192];
__device__ bf16 g_w2t    [192 * 768];

// ---------------- helpers ----------------
__device__ __forceinline__ size_t token_src_offset(int t) {
    int wi = t / 24, n = t % 24;
    int i3 = n / 12, j3 = (n >> 1) % 6, k3 = n & 1;
    int d0 = wi % 7;  int r = wi / 7;
    int w0 = r % 16;  r /= 16;
    int h0 = r % 24;  int b0 = r / 24;
    return ((((size_t)b0 * 48 + (h0 * 2 + i3)) * 96 + (w0 * 6 + j3)) * 14
            + (d0 * 2 + k3)) * 192;
}
__device__ __forceinline__ float warp_sum(float v) {
#pragma unroll
    for (int o = 16; o; o >>= 1) v += __shfl_xor_sync(0xffffffffu, v, o);
    return v;
}
__device__ __forceinline__ float warp_max(float v) {
#pragma unroll
    for (int o = 16; o; o >>= 1) v = fmaxf(v, __shfl_xor_sync(0xffffffffu, v, o));
    return v;
}
__device__ __forceinline__ uint32_t smem_u32(const void* p) {
    uint32_t a;
    asm("{ .reg .u64 t; cvta.to.shared.u64 t, %1; cvt.u32.u64 %0, t; }" : "=r"(a) : "l"(p));
    return a;
}
__device__ __forceinline__ void cp16(uint32_t dst, const void* src) {
    asm volatile("cp.async.cg.shared.global [%0], [%1], 16;" :: "r"(dst), "l"(src));
}
#define CP_COMMIT() asm volatile("cp.async.commit_group;" ::: "memory")
#define CP_WAIT(n)  asm volatile("cp.async.wait_group %0;" :: "n"(n) : "memory")

__device__ __forceinline__ void ldsm_x4(uint32_t* r, uint32_t a) {
    asm volatile("ldmatrix.sync.aligned.m8n8.x4.shared.b16 {%0,%1,%2,%3}, [%4];"
                 : "=r"(r[0]), "=r"(r[1]), "=r"(r[2]), "=r"(r[3]) : "r"(a));
}
__device__ __forceinline__ void mma_bf16(float* d, const uint32_t* a,
                                         const uint32_t* b, const float* c) {
    asm volatile(
        "mma.sync.aligned.m16n8k16.row.col.f32.bf16.bf16.f32 "
        "{%0,%1,%2,%3}, {%4,%5,%6,%7}, {%8,%9}, {%10,%11,%12,%13};"
        : "=f"(d[0]), "=f"(d[1]), "=f"(d[2]), "=f"(d[3])
        : "r"(a[0]), "r"(a[1]), "r"(a[2]), "r"(a[3]),
          "r"(b[0]), "r"(b[1]),
          "f"(c[0]), "f"(c[1]), "f"(c[2]), "f"(c[3]));
}

// ---------------- weight transpose [K,N] -> bf16 [N,K] ----------------
__global__ void transpose_kernel(const float* __restrict__ W, bf16* __restrict__ Wt,
                                 int K, int N) {
    __shared__ float t[32][33];
    int kb = blockIdx.x * 32, nb = blockIdx.y * 32;
    int x = threadIdx.x, y = threadIdx.y;
#pragma unroll
    for (int j = 0; j < 32; j += 8) t[y + j][x] = W[(size_t)(kb + y + j) * N + nb + x];
    __syncthreads();
#pragma unroll
    for (int j = 0; j < 32; j += 8)
        Wt[(size_t)(nb + y + j) * K + kb + x] = __float2bfloat16(t[x][y + j]);
}

// ---------------- gather + LN1 ----------------
__global__ __launch_bounds__(256) void gather_ln1_kernel(
    const float* __restrict__ x, const float* __restrict__ gam, const float* __restrict__ bet)
{
    int t = blockIdx.x * 8 + (threadIdx.x >> 5);
    int lane = threadIdx.x & 31;
    size_t src = token_src_offset(t);
    float v[6]; float s = 0.f;
#pragma unroll
    for (int q = 0; q < 6; q++) { v[q] = x[src + lane + q * 32]; s += v[q]; }
    float mean = warp_sum(s) * (1.0f / 192.0f);
    float vs = 0.f;
#pragma unroll
    for (int q = 0; q < 6; q++) { float d = v[q] - mean; vs += d * d; }
    float rstd = rsqrtf(warp_sum(vs) * (1.0f / 192.0f) + 1e-5f);
    size_t dst = (size_t)t * 192;
#pragma unroll
    for (int q = 0; q < 6; q++) {
        int c = lane + q * 32;
        g_xw[dst + c] = v[q];
        g_h [dst + c] = __float2bfloat16((v[q] - mean) * rstd * gam[c] + bet[c]);
    }
}

// ---------------- LN2 ----------------
__global__ __launch_bounds__(256) void ln2_kernel(
    const float* __restrict__ gam, const float* __restrict__ bet)
{
    int t = blockIdx.x * 8 + (threadIdx.x >> 5);
    int lane = threadIdx.x & 31;
    size_t base = (size_t)t * 192;
    float v[6]; float s = 0.f;
#pragma unroll
    for (int q = 0; q < 6; q++) { v[q] = g_x2[base + lane + q * 32]; s += v[q]; }
    float mean = warp_sum(s) * (1.0f / 192.0f);
    float vs = 0.f;
#pragma unroll
    for (int q = 0; q < 6; q++) { float d = v[q] - mean; vs += d * d; }
    float rstd = rsqrtf(warp_sum(vs) * (1.0f / 192.0f) + 1e-5f);
#pragma unroll
    for (int q = 0; q < 6; q++) {
        int c = lane + q * 32;
        g_h[base + c] = __float2bfloat16((v[q] - mean) * rstd * gam[c] + bet[c]);
    }
}

// ---------------- attention (per-window, fp32 math, bf16 I/O) ----------------
__global__ __launch_bounds__(192) void attn_kernel(
    const float* __restrict__ bias_table, const int* __restrict__ rel_index)
{
    __shared__ float q_s[HEADS][24][32];
    __shared__ float v_s[HEADS][24][33];
    __shared__ int   rel_s[576];
    const int wi = blockIdx.x;
    const int h = threadIdx.x >> 5, lane = threadIdx.x & 31;
    const bf16* base = g_qkv + (size_t)wi * 24 * 576;
    for (int idx = threadIdx.x; idx < 576; idx += 192) rel_s[idx] = rel_index[idx];
#pragma unroll
    for (int n = 0; n < 24; n++) {
        q_s[h][n][lane] = __bfloat162float(base[n * 576 +       h * 32 + lane]);
        v_s[h][n][lane] = __bfloat162float(base[n * 576 + 384 + h * 32 + lane]);
    }
    __syncthreads();
    float kr[32];
    if (lane < 24) {
        const bf16* kp = base + lane * 576 + 192 + h * 32;
#pragma unroll
        for (int d = 0; d < 32; d += 2) {
            __nv_bfloat162 k2 = *(const __nv_bfloat162*)(kp + d);
            kr[d] = __bfloat162float(k2.x); kr[d + 1] = __bfloat162float(k2.y);
        }
    }
    const float scale = 0.17677669529663687f;
    float s[24];
    if (lane < 24) {
#pragma unroll 4
        for (int n = 0; n < 24; n++) {
            float a = 0.f;
#pragma unroll
            for (int d = 0; d < 32; d += 4) {
                float4 q4 = *(const float4*)&q_s[h][n][d];
                a = fmaf(q4.x, kr[d], a); a = fmaf(q4.y, kr[d+1], a);
                a = fmaf(q4.z, kr[d+2], a); a = fmaf(q4.w, kr[d+3], a);
            }
            s[n] = a * scale + bias_table[rel_s[n * 24 + lane] * HEADS + h];
        }
    } else {
#pragma unroll
        for (int n = 0; n < 24; n++) s[n] = -1e30f;
    }
    __syncwarp();
#pragma unroll 4
    for (int n = 0; n < 24; n++) {
        float mx = warp_max(s[n]);
        float e = (lane < 24) ? __expf(s[n] - mx) : 0.f;
        float sm = warp_sum(e);
        if (lane < 24) q_s[h][n][lane] = e / sm;
    }
    __syncwarp();
    float vcol[24];
#pragma unroll
    for (int m = 0; m < 24; m++) vcol[m] = v_s[h][m][lane];
    bf16* ob = g_attn + (size_t)wi * 24 * 192 + h * 32 + lane;
#pragma unroll 4
    for (int n = 0; n < 24; n++) {
        float a = 0.f;
#pragma unroll
        for (int m4 = 0; m4 < 24; m4 += 4) {
            float4 p4 = *(const float4*)&q_s[h][n][m4];
            a = fmaf(p4.x, vcol[m4], a); a = fmaf(p4.y, vcol[m4+1], a);
            a = fmaf(p4.z, vcol[m4+2], a); a = fmaf(p4.w, vcol[m4+3], a);
        }
        ob[n * 192] = __float2bfloat16(a);
    }
}

// ---------------- bf16 tensor GEMM: C = A[M,K] @ Bt[N,K]^T + epilogue ------
// BM=128, BN=96, BK=32, 8 warps (4x2), warp tile 32x48 = 2x6 m16n8k16.
// cp.async double buffer, ldmatrix fragments, smem row stride 40 halves (80B).
// blockIdx.x = col block (fast -> L2 A-reuse), blockIdx.y = row block.
// EPI: 0 bias->bf16, 1 bias+gelu->bf16, 2 bias+res->fp32, 3 bias+res+scatter->fp32
template <int EPI>
__global__ __launch_bounds__(256) void tc_gemm(
    const bf16* __restrict__ A, const bf16* __restrict__ Bt,
    const float* __restrict__ bias, const float* __restrict__ res,
    void* __restrict__ Cc, int N, int K)
{
    constexpr int LDA = 40;   // halves per smem row
    __shared__ __align__(16) bf16 As[2][128 * LDA];
    __shared__ __align__(16) bf16 Bs[2][96 * LDA];

    const int tid  = threadIdx.x;
    const int lane = tid & 31;
    const int wid  = tid >> 5;
    const int wm   = wid & 3;
    const int wn   = wid >> 2;
    const int col0 = blockIdx.x * 96;
    const int row0 = blockIdx.y * 128;

    const int gq = lane >> 2, tg = lane & 3;
    const uint32_t sA[2] = { smem_u32(As[0]), smem_u32(As[1]) };
    const uint32_t sB[2] = { smem_u32(Bs[0]), smem_u32(Bs[1]) };

    float acc[2][6][4];
#pragma unroll
    for (int mi = 0; mi < 2; mi++)
#pragma unroll
        for (int ni = 0; ni < 6; ni++)
#pragma unroll
            for (int j = 0; j < 4; j++) acc[mi][ni][j] = 0.f;

    const int nstages = K / 32;

    auto prefetch = [&](int s, int b) {
        const bf16* Ag = A + (size_t)row0 * K + s * 32;
        const bf16* Bg = Bt + (size_t)col0 * K + s * 32;
        // A: 128 rows x 32 halves = 512 x 16B chunks
#pragma unroll
        for (int j = 0; j < 2; j++) {
            int idx = tid + j * 256;
            int r = idx >> 2, c = idx & 3;
            cp16(sA[b] + (uint32_t)(r * 80 + c * 16), Ag + (size_t)r * K + c * 8);
        }
        // B: 96 rows x 32 halves = 384 chunks
        {
            int idx = tid;
            int r = idx >> 2, c = idx & 3;
            cp16(sB[b] + (uint32_t)(r * 80 + c * 16), Bg + (size_t)r * K + c * 8);
        }
        if (tid < 128) {
            int idx = tid + 256;
            int r = idx >> 2, c = idx & 3;
            cp16(sB[b] + (uint32_t)(r * 80 + c * 16), Bg + (size_t)r * K + c * 8);
        }
        CP_COMMIT();
    };

    prefetch(0, 0);

    for (int s = 0; s < nstages; s++) {
        const int b = s & 1;
        if (s + 1 < nstages) { prefetch(s + 1, b ^ 1); CP_WAIT(1); }
        else                 { CP_WAIT(0); }
        __syncthreads();

#pragma unroll
        for (int kk = 0; kk < 32; kk += 16) {
            uint32_t afr[2][4];
            const int arow = wm * 32 + (lane & 15);
            const int acol = kk + (lane >> 4) * 8;
#pragma unroll
            for (int mi = 0; mi < 2; mi++)
                ldsm_x4(afr[mi], sA[b] + (uint32_t)(((arow + mi * 16) * LDA + acol) * 2));

            uint32_t bfr[6][2];
#pragma unroll
            for (int p = 0; p < 3; p++) {
                const int brow = wn * 48 + p * 16 + (lane & 7) + ((lane >> 4) << 3);
                const int bcol = kk + ((lane >> 3) & 1) * 8;
                uint32_t r4[4];
                ldsm_x4(r4, sB[b] + (uint32_t)((brow * LDA + bcol) * 2));
                bfr[2*p][0] = r4[0]; bfr[2*p][1] = r4[1];
                bfr[2*p+1][0] = r4[2]; bfr[2*p+1][1] = r4[3];
            }
#pragma unroll
            for (int mi = 0; mi < 2; mi++)
#pragma unroll
                for (int ni = 0; ni < 6; ni++)
                    mma_bf16(acc[mi][ni], afr[mi], bfr[ni], acc[mi][ni]);
        }
        __syncthreads();
    }

    // ---- epilogue ----
#pragma unroll
    for (int mi = 0; mi < 2; mi++) {
#pragma unroll
        for (int ni = 0; ni < 6; ni++) {
            int row = row0 + wm * 32 + mi * 16 + gq;
            int col = col0 + wn * 48 + ni * 8 + tg * 2;
            float b0 = bias[col], b1 = bias[col + 1];
#pragma unroll
            for (int hh = 0; hh < 2; hh++) {
                int r = row + hh * 8;
                float v0 = acc[mi][ni][hh * 2]     + b0;
                float v1 = acc[mi][ni][hh * 2 + 1] + b1;
                if (EPI == 1) {
                    v0 = 0.5f * v0 * (1.0f + erff(v0 * 0.70710678118654752f));
                    v1 = 0.5f * v1 * (1.0f + erff(v1 * 0.70710678118654752f));
                }
                if (EPI >= 2) {
                    const float* rp = res + (size_t)r * 192 + col;
                    v0 += rp[0]; v1 += rp[1];
                }
                if (EPI <= 1) {
                    bf16* cp_ = (bf16*)Cc + (size_t)r * N + col;
                    *(__nv_bfloat162*)cp_ = __floats2bfloat162_rn(v0, v1);
                } else {
                    size_t off = (EPI == 3) ? token_src_offset(r) + col
                                            : (size_t)r * N + col;
                    *(float2*)((float*)Cc + off) = make_float2(v0, v1);
                }
            }
        }
    }
}

// ---------------- host launcher ----------------
extern "C" void kernel_launch(void* const* d_in, const int* in_sizes, int n_in,
                              void* d_out, int out_size)
{
    const float* x      = (const float*)d_in[0];
    const float* ln1_g  = (const float*)d_in[1];
    const float* ln1_b  = (const float*)d_in[2];
    const float* qkv_w  = (const float*)d_in[3];
    const float* qkv_b  = (const float*)d_in[4];
    const float* btab   = (const float*)d_in[5];
    const float* proj_w = (const float*)d_in[6];
    const float* proj_b = (const float*)d_in[7];
    const float* ln2_g  = (const float*)d_in[8];
    const float* ln2_b  = (const float*)d_in[9];
    const float* mlp_w1 = (const float*)d_in[10];
    const float* mlp_b1 = (const float*)d_in[11];
    const float* mlp_w2 = (const float*)d_in[12];
    const float* mlp_b2 = (const float*)d_in[13];
    const int*   rel_idx= (const int*)d_in[14];
    float*       out    = (float*)d_out;

    bf16 *p_h, *p_qkv, *p_attn, *p_hid;
    float *p_x2, *p_xw;
    bf16 *p_qkv_wt, *p_proj_wt, *p_w1t, *p_w2t;
    cudaGetSymbolAddress((void**)&p_xw,   g_xw);
    cudaGetSymbolAddress((void**)&p_h,    g_h);
    cudaGetSymbolAddress((void**)&p_qkv,  g_qkv);
    cudaGetSymbolAddress((void**)&p_attn, g_attn);
    cudaGetSymbolAddress((void**)&p_x2,   g_x2);
    cudaGetSymbolAddress((void**)&p_hid,  g_hid);
    cudaGetSymbolAddress((void**)&p_qkv_wt,  g_qkv_wt);
    cudaGetSymbolAddress((void**)&p_proj_wt, g_proj_wt);
    cudaGetSymbolAddress((void**)&p_w1t,  g_w1t);
    cudaGetSymbolAddress((void**)&p_w2t,  g_w2t);

    dim3 tb(32, 8);
    transpose_kernel<<<dim3(6, 18), tb>>>(qkv_w,  p_qkv_wt,  192, 576);
    transpose_kernel<<<dim3(6, 6),  tb>>>(proj_w, p_proj_wt, 192, 192);
    transpose_kernel<<<dim3(6, 24), tb>>>(mlp_w1, p_w1t,     192, 768);
    transpose_kernel<<<dim3(24, 6), tb>>>(mlp_w2, p_w2t,     768, 192);

    gather_ln1_kernel<<<NTOK_TOTAL / 8, 256>>>(x, ln1_g, ln1_b);

    const int Mb = NTOK_TOTAL / 128;  // 1008
    // QKV: [T,192] @ [192,576]
    tc_gemm<0><<<dim3(6, Mb), 256>>>(p_h, p_qkv_wt, qkv_b, nullptr, p_qkv, 576, 192);
    // attention
    attn_kernel<<<NWIN, 192>>>(btab, rel_idx);
    // proj + residual -> fp32 trunk
    tc_gemm<2><<<dim3(2, Mb), 256>>>(p_attn, p_proj_wt, proj_b, p_xw, p_x2, 192, 192);
    // LN2
    ln2_kernel<<<NTOK_TOTAL / 8, 256>>>(ln2_g, ln2_b);
    // MLP1 + gelu
    tc_gemm<1><<<dim3(8, Mb), 256>>>(p_h, p_w1t, mlp_b1, nullptr, p_hid, 768, 192);
    // MLP2 + residual + scatter
    tc_gemm<3><<<dim3(2, Mb), 256>>>(p_hid, p_w2t, mlp_b2, p_x2, out, 192, 768);
}

// round 5
// speedup vs baseline: 3.4286x; 1.0998x over previous
#include <cuda_runtime.h>
#include <cuda_bf16.h>
#include <math.h>
#include <stdint.h>

typedef __nv_bfloat16 bf16;

// ---------------- problem constants ----------------
#define NTOK_TOTAL 129024   // 5376 windows * 24 tokens
#define NWIN       5376
#define HEADS      6

// ---------------- scratch (device globals) ----------------
__device__ float g_x2  [(size_t)NTOK_TOTAL * 192];   // trunk after proj (fp32)
__device__ bf16  g_h   [(size_t)NTOK_TOTAL * 192];   // LN out (bf16, GEMM A)
__device__ bf16  g_qkv [(size_t)NTOK_TOTAL * 576];
__device__ bf16  g_attn[(size_t)NTOK_TOTAL * 192];
__device__ bf16  g_hid [(size_t)NTOK_TOTAL * 768];
// pre-transposed bf16 weights (K-major: Wt[N][K])
__device__ bf16 g_qkv_wt [576 * 192];
__device__ bf16 g_proj_wt[192 * 192];
__device__ bf16 g_w1t    [768 * 192];
__device__ bf16 g_w2t    [192 * 768];

// ---------------- helpers ----------------
__device__ __forceinline__ size_t token_src_offset(int t) {
    int wi = t / 24, n = t % 24;
    int i3 = n / 12, j3 = (n >> 1) % 6, k3 = n & 1;
    int d0 = wi % 7;  int r = wi / 7;
    int w0 = r % 16;  r /= 16;
    int h0 = r % 24;  int b0 = r / 24;
    return ((((size_t)b0 * 48 + (h0 * 2 + i3)) * 96 + (w0 * 6 + j3)) * 14
            + (d0 * 2 + k3)) * 192;
}
__device__ __forceinline__ float warp_sum(float v) {
#pragma unroll
    for (int o = 16; o; o >>= 1) v += __shfl_xor_sync(0xffffffffu, v, o);
    return v;
}
__device__ __forceinline__ float warp_max(float v) {
#pragma unroll
    for (int o = 16; o; o >>= 1) v = fmaxf(v, __shfl_xor_sync(0xffffffffu, v, o));
    return v;
}
__device__ __forceinline__ uint32_t smem_u32(const void* p) {
    uint32_t a;
    asm("{ .reg .u64 t; cvta.to.shared.u64 t, %1; cvt.u32.u64 %0, t; }" : "=r"(a) : "l"(p));
    return a;
}
__device__ __forceinline__ void cp16(uint32_t dst, const void* src) {
    asm volatile("cp.async.cg.shared.global [%0], [%1], 16;" :: "r"(dst), "l"(src));
}
#define CP_COMMIT() asm volatile("cp.async.commit_group;" ::: "memory")
#define CP_WAIT(n)  asm volatile("cp.async.wait_group %0;" :: "n"(n) : "memory")

__device__ __forceinline__ void ldsm_x4(uint32_t* r, uint32_t a) {
    asm volatile("ldmatrix.sync.aligned.m8n8.x4.shared.b16 {%0,%1,%2,%3}, [%4];"
                 : "=r"(r[0]), "=r"(r[1]), "=r"(r[2]), "=r"(r[3]) : "r"(a));
}
__device__ __forceinline__ void mma_bf16(float* d, const uint32_t* a,
                                         const uint32_t* b, const float* c) {
    asm volatile(
        "mma.sync.aligned.m16n8k16.row.col.f32.bf16.bf16.f32 "
        "{%0,%1,%2,%3}, {%4,%5,%6,%7}, {%8,%9}, {%10,%11,%12,%13};"
        : "=f"(d[0]), "=f"(d[1]), "=f"(d[2]), "=f"(d[3])
        : "r"(a[0]), "r"(a[1]), "r"(a[2]), "r"(a[3]),
          "r"(b[0]), "r"(b[1]),
          "f"(c[0]), "f"(c[1]), "f"(c[2]), "f"(c[3]));
}

// ---------------- one-shot weight transpose (all 4 weights) ----------------
// 432 blocks of 32x32 tiles:
// [0,108): qkv_w (192x576)  [108,144): proj_w (192x192)
// [144,288): mlp_w1 (192x768)  [288,432): mlp_w2 (768x192)
__global__ void transpose_all_kernel(
    const float* __restrict__ qkv_w, const float* __restrict__ proj_w,
    const float* __restrict__ w1, const float* __restrict__ w2,
    bf16* __restrict__ qkv_wt, bf16* __restrict__ proj_wt,
    bf16* __restrict__ w1t, bf16* __restrict__ w2t)
{
    __shared__ float t[32][33];
    int bid = blockIdx.x;
    const float* W; bf16* Wt; int K, N, loc;
    if (bid < 108)      { W = qkv_w;  Wt = qkv_wt;  K = 192; N = 576; loc = bid; }
    else if (bid < 144) { W = proj_w; Wt = proj_wt; K = 192; N = 192; loc = bid - 108; }
    else if (bid < 288) { W = w1;     Wt = w1t;     K = 192; N = 768; loc = bid - 144; }
    else                { W = w2;     Wt = w2t;     K = 768; N = 192; loc = bid - 288; }
    int Kt = K / 32;
    int kb = (loc % Kt) * 32, nb = (loc / Kt) * 32;
    int x = threadIdx.x, y = threadIdx.y;
#pragma unroll
    for (int j = 0; j < 32; j += 8) t[y + j][x] = W[(size_t)(kb + y + j) * N + nb + x];
    __syncthreads();
#pragma unroll
    for (int j = 0; j < 32; j += 8)
        Wt[(size_t)(nb + y + j) * K + kb + x] = __float2bfloat16(t[x][y + j]);
}

// ---------------- gather + LN1 (no raw copy; residual re-gathered later) ----
__global__ __launch_bounds__(256) void gather_ln1_kernel(
    const float* __restrict__ x, const float* __restrict__ gam, const float* __restrict__ bet)
{
    int t = blockIdx.x * 8 + (threadIdx.x >> 5);
    int lane = threadIdx.x & 31;
    size_t src = token_src_offset(t);
    float v[6]; float s = 0.f;
#pragma unroll
    for (int q = 0; q < 6; q++) { v[q] = x[src + lane + q * 32]; s += v[q]; }
    float mean = warp_sum(s) * (1.0f / 192.0f);
    float vs = 0.f;
#pragma unroll
    for (int q = 0; q < 6; q++) { float d = v[q] - mean; vs += d * d; }
    float rstd = rsqrtf(warp_sum(vs) * (1.0f / 192.0f) + 1e-5f);
    size_t dst = (size_t)t * 192;
#pragma unroll
    for (int q = 0; q < 6; q++) {
        int c = lane + q * 32;
        g_h[dst + c] = __float2bfloat16((v[q] - mean) * rstd * gam[c] + bet[c]);
    }
}

// ---------------- attention (per-window, fp32 math, bf16 I/O) ----------------
__global__ __launch_bounds__(192) void attn_kernel(
    const float* __restrict__ bias_table, const int* __restrict__ rel_index)
{
    __shared__ float q_s[HEADS][24][32];
    __shared__ float v_s[HEADS][24][33];
    __shared__ int   rel_s[576];
    const int wi = blockIdx.x;
    const int h = threadIdx.x >> 5, lane = threadIdx.x & 31;
    const bf16* base = g_qkv + (size_t)wi * 24 * 576;
    for (int idx = threadIdx.x; idx < 576; idx += 192) rel_s[idx] = rel_index[idx];
#pragma unroll
    for (int n = 0; n < 24; n++) {
        q_s[h][n][lane] = __bfloat162float(base[n * 576 +       h * 32 + lane]);
        v_s[h][n][lane] = __bfloat162float(base[n * 576 + 384 + h * 32 + lane]);
    }
    __syncthreads();
    float kr[32];
    if (lane < 24) {
        const bf16* kp = base + lane * 576 + 192 + h * 32;
#pragma unroll
        for (int d = 0; d < 32; d += 2) {
            __nv_bfloat162 k2 = *(const __nv_bfloat162*)(kp + d);
            kr[d] = __bfloat162float(k2.x); kr[d + 1] = __bfloat162float(k2.y);
        }
    }
    const float scale = 0.17677669529663687f;
    float s[24];
    if (lane < 24) {
#pragma unroll 4
        for (int n = 0; n < 24; n++) {
            float a = 0.f;
#pragma unroll
            for (int d = 0; d < 32; d += 4) {
                float4 q4 = *(const float4*)&q_s[h][n][d];
                a = fmaf(q4.x, kr[d], a); a = fmaf(q4.y, kr[d+1], a);
                a = fmaf(q4.z, kr[d+2], a); a = fmaf(q4.w, kr[d+3], a);
            }
            s[n] = a * scale + bias_table[rel_s[n * 24 + lane] * HEADS + h];
        }
    } else {
#pragma unroll
        for (int n = 0; n < 24; n++) s[n] = -1e30f;
    }
    __syncwarp();
#pragma unroll 4
    for (int n = 0; n < 24; n++) {
        float mx = warp_max(s[n]);
        float e = (lane < 24) ? __expf(s[n] - mx) : 0.f;
        float sm = warp_sum(e);
        if (lane < 24) q_s[h][n][lane] = e / sm;
    }
    __syncwarp();
    float vcol[24];
#pragma unroll
    for (int m = 0; m < 24; m++) vcol[m] = v_s[h][m][lane];
    bf16* ob = g_attn + (size_t)wi * 24 * 192 + h * 32 + lane;
#pragma unroll 4
    for (int n = 0; n < 24; n++) {
        float a = 0.f;
#pragma unroll
        for (int m4 = 0; m4 < 24; m4 += 4) {
            float4 p4 = *(const float4*)&q_s[h][n][m4];
            a = fmaf(p4.x, vcol[m4], a); a = fmaf(p4.y, vcol[m4+1], a);
            a = fmaf(p4.z, vcol[m4+2], a); a = fmaf(p4.w, vcol[m4+3], a);
        }
        ob[n * 192] = __float2bfloat16(a);
    }
}

// ======================= generic bf16 GEMM (BN=96) ==========================
// BM=128, BN=96, BK=32, 8 warps (4x2), warp tile 32x48, 3-stage cp.async.
// EPI: 0 bias->bf16, 1 bias+gelu->bf16, 3 bias+res+scatter->fp32
#define GEMM_SMEM (3 * (128 + 96) * 40 * 2)
template <int EPI>
__global__ __launch_bounds__(256) void tc_gemm(
    const bf16* __restrict__ A, const bf16* __restrict__ Bt,
    const float* __restrict__ bias, const float* __restrict__ res,
    void* __restrict__ Cc, int N, int K)
{
    constexpr int LDA = 40;
    constexpr int ASZ = 128 * LDA, BSZ = 96 * LDA;   // halves per buffer
    extern __shared__ bf16 smem[];
    bf16* Asb = smem;
    bf16* Bsb = smem + 3 * ASZ;

    const int tid  = threadIdx.x;
    const int lane = tid & 31;
    const int wid  = tid >> 5;
    const int wm   = wid & 3;
    const int wn   = wid >> 2;
    const int col0 = blockIdx.x * 96;
    const int row0 = blockIdx.y * 128;
    const int gq = lane >> 2, tg = lane & 3;

    const uint32_t sAb = smem_u32(Asb), sBb = smem_u32(Bsb);

    float acc[2][6][4];
#pragma unroll
    for (int mi = 0; mi < 2; mi++)
#pragma unroll
        for (int ni = 0; ni < 6; ni++)
#pragma unroll
            for (int j = 0; j < 4; j++) acc[mi][ni][j] = 0.f;

    const int nstages = K / 32;

    auto prefetch = [&](int s, int b) {
        const bf16* Ag = A + (size_t)row0 * K + s * 32;
        const bf16* Bg = Bt + (size_t)col0 * K + s * 32;
        uint32_t sA = sAb + (uint32_t)b * ASZ * 2;
        uint32_t sB = sBb + (uint32_t)b * BSZ * 2;
#pragma unroll
        for (int j = 0; j < 2; j++) {
            int idx = tid + j * 256;
            int r = idx >> 2, c = idx & 3;
            cp16(sA + (uint32_t)(r * 80 + c * 16), Ag + (size_t)r * K + c * 8);
        }
        {
            int r = tid >> 2, c = tid & 3;
            cp16(sB + (uint32_t)(r * 80 + c * 16), Bg + (size_t)r * K + c * 8);
        }
        if (tid < 128) {
            int idx = tid + 256;
            int r = idx >> 2, c = idx & 3;
            cp16(sB + (uint32_t)(r * 80 + c * 16), Bg + (size_t)r * K + c * 8);
        }
        CP_COMMIT();
    };

    prefetch(0, 0);
    prefetch(1, 1);

    for (int s = 0; s < nstages; s++) {
        if (s < nstages - 1) CP_WAIT(1); else CP_WAIT(0);
        __syncthreads();
        if (s + 2 < nstages) prefetch(s + 2, (s + 2) % 3);

        const int b = s % 3;
        const uint32_t sA = sAb + (uint32_t)b * ASZ * 2;
        const uint32_t sB = sBb + (uint32_t)b * BSZ * 2;
#pragma unroll
        for (int kk = 0; kk < 32; kk += 16) {
            uint32_t afr[2][4];
            const int arow = wm * 32 + (lane & 15);
            const int acol = kk + (lane >> 4) * 8;
#pragma unroll
            for (int mi = 0; mi < 2; mi++)
                ldsm_x4(afr[mi], sA + (uint32_t)(((arow + mi * 16) * LDA + acol) * 2));

            uint32_t bfr[6][2];
#pragma unroll
            for (int p = 0; p < 3; p++) {
                const int brow = wn * 48 + p * 16 + (lane & 7) + ((lane >> 4) << 3);
                const int bcol = kk + ((lane >> 3) & 1) * 8;
                uint32_t r4[4];
                ldsm_x4(r4, sB + (uint32_t)((brow * LDA + bcol) * 2));
                bfr[2*p][0] = r4[0]; bfr[2*p][1] = r4[1];
                bfr[2*p+1][0] = r4[2]; bfr[2*p+1][1] = r4[3];
            }
#pragma unroll
            for (int mi = 0; mi < 2; mi++)
#pragma unroll
                for (int ni = 0; ni < 6; ni++)
                    mma_bf16(acc[mi][ni], afr[mi], bfr[ni], acc[mi][ni]);
        }
    }

    // ---- epilogue ----
#pragma unroll
    for (int mi = 0; mi < 2; mi++) {
#pragma unroll
        for (int ni = 0; ni < 6; ni++) {
            int row = row0 + wm * 32 + mi * 16 + gq;
            int col = col0 + wn * 48 + ni * 8 + tg * 2;
            float b0 = bias[col], b1 = bias[col + 1];
#pragma unroll
            for (int hh = 0; hh < 2; hh++) {
                int r = row + hh * 8;
                float v0 = acc[mi][ni][hh * 2]     + b0;
                float v1 = acc[mi][ni][hh * 2 + 1] + b1;
                if (EPI == 1) {
                    v0 = 0.5f * v0 * (1.0f + erff(v0 * 0.70710678118654752f));
                    v1 = 0.5f * v1 * (1.0f + erff(v1 * 0.70710678118654752f));
                }
                if (EPI == 3) {
                    const float* rp = res + (size_t)r * 192 + col;
                    v0 += rp[0]; v1 += rp[1];
                    size_t off = token_src_offset(r) + col;
                    *(float2*)((float*)Cc + off) = make_float2(v0, v1);
                } else {
                    bf16* cp_ = (bf16*)Cc + (size_t)r * N + col;
                    *(__nv_bfloat162*)cp_ = __floats2bfloat162_rn(v0, v1);
                }
            }
        }
    }
}

// ================= proj GEMM (BN=192, full row) + residual + LN2 ============
// out trunk -> g_x2 (fp32), LN2(out) -> g_h (bf16). Residual gathered from x.
#define PROJ_SMEM (3 * (128 + 192) * 40 * 2)
__global__ __launch_bounds__(256) void proj_ln2_kernel(
    const bf16* __restrict__ A, const bf16* __restrict__ Bt,
    const float* __restrict__ bias, const float* __restrict__ x,
    const float* __restrict__ gam, const float* __restrict__ bet)
{
    constexpr int LDA = 40, K = 192;
    constexpr int ASZ = 128 * LDA, BSZ = 192 * LDA;
    extern __shared__ bf16 smem[];
    bf16* Asb = smem;
    bf16* Bsb = smem + 3 * ASZ;
    __shared__ float s_sum[128][2];
    __shared__ float s_sq [128][2];

    const int tid  = threadIdx.x;
    const int lane = tid & 31;
    const int wid  = tid >> 5;
    const int wm   = wid & 3;
    const int wn   = wid >> 2;
    const int row0 = blockIdx.x * 128;
    const int gq = lane >> 2, tg = lane & 3;

    const uint32_t sAb = smem_u32(Asb), sBb = smem_u32(Bsb);

    float acc[2][12][4];
#pragma unroll
    for (int mi = 0; mi < 2; mi++)
#pragma unroll
        for (int ni = 0; ni < 12; ni++)
#pragma unroll
            for (int j = 0; j < 4; j++) acc[mi][ni][j] = 0.f;

    const int nstages = 6;

    auto prefetch = [&](int s, int b) {
        const bf16* Ag = A + (size_t)row0 * K + s * 32;
        const bf16* Bg = Bt + (size_t)s * 32;
        uint32_t sA = sAb + (uint32_t)b * ASZ * 2;
        uint32_t sB = sBb + (uint32_t)b * BSZ * 2;
#pragma unroll
        for (int j = 0; j < 2; j++) {
            int idx = tid + j * 256;
            int r = idx >> 2, c = idx & 3;
            cp16(sA + (uint32_t)(r * 80 + c * 16), Ag + (size_t)r * K + c * 8);
        }
#pragma unroll
        for (int j = 0; j < 3; j++) {
            int idx = tid + j * 256;
            int r = idx >> 2, c = idx & 3;
            cp16(sB + (uint32_t)(r * 80 + c * 16), Bg + (size_t)r * K + c * 8);
        }
        CP_COMMIT();
    };

    prefetch(0, 0);
    prefetch(1, 1);

    for (int s = 0; s < nstages; s++) {
        if (s < nstages - 1) CP_WAIT(1); else CP_WAIT(0);
        __syncthreads();
        if (s + 2 < nstages) prefetch(s + 2, (s + 2) % 3);

        const int b = s % 3;
        const uint32_t sA = sAb + (uint32_t)b * ASZ * 2;
        const uint32_t sB = sBb + (uint32_t)b * BSZ * 2;
#pragma unroll
        for (int kk = 0; kk < 32; kk += 16) {
            uint32_t afr[2][4];
            const int arow = wm * 32 + (lane & 15);
            const int acol = kk + (lane >> 4) * 8;
#pragma unroll
            for (int mi = 0; mi < 2; mi++)
                ldsm_x4(afr[mi], sA + (uint32_t)(((arow + mi * 16) * LDA + acol) * 2));

            uint32_t bfr[12][2];
#pragma unroll
            for (int p = 0; p < 6; p++) {
                const int brow = wn * 96 + p * 16 + (lane & 7) + ((lane >> 4) << 3);
                const int bcol = kk + ((lane >> 3) & 1) * 8;
                uint32_t r4[4];
                ldsm_x4(r4, sB + (uint32_t)((brow * LDA + bcol) * 2));
                bfr[2*p][0] = r4[0]; bfr[2*p][1] = r4[1];
                bfr[2*p+1][0] = r4[2]; bfr[2*p+1][1] = r4[3];
            }
#pragma unroll
            for (int mi = 0; mi < 2; mi++)
#pragma unroll
                for (int ni = 0; ni < 12; ni++)
                    mma_bf16(acc[mi][ni], afr[mi], bfr[ni], acc[mi][ni]);
        }
    }

    // ---- epilogue: bias + residual(from x) + row stats ----
#pragma unroll
    for (int mi = 0; mi < 2; mi++) {
#pragma unroll
        for (int hh = 0; hh < 2; hh++) {
            int rl = wm * 32 + mi * 16 + gq + hh * 8;
            int r  = row0 + rl;
            size_t roff = token_src_offset(r);
            float s1 = 0.f, s2 = 0.f;
#pragma unroll
            for (int ni = 0; ni < 12; ni++) {
                int col = wn * 96 + ni * 8 + tg * 2;
                float2 rx = *(const float2*)(x + roff + col);
                float v0 = acc[mi][ni][hh*2]     + bias[col]     + rx.x;
                float v1 = acc[mi][ni][hh*2 + 1] + bias[col + 1] + rx.y;
                acc[mi][ni][hh*2]     = v0;
                acc[mi][ni][hh*2 + 1] = v1;
                s1 += v0 + v1;
                s2 += v0 * v0 + v1 * v1;
            }
            s1 += __shfl_xor_sync(0xffffffffu, s1, 1);
            s1 += __shfl_xor_sync(0xffffffffu, s1, 2);
            s2 += __shfl_xor_sync(0xffffffffu, s2, 1);
            s2 += __shfl_xor_sync(0xffffffffu, s2, 2);
            if (tg == 0) { s_sum[rl][wn] = s1; s_sq[rl][wn] = s2; }
        }
    }
    __syncthreads();
#pragma unroll
    for (int mi = 0; mi < 2; mi++) {
#pragma unroll
        for (int hh = 0; hh < 2; hh++) {
            int rl = wm * 32 + mi * 16 + gq + hh * 8;
            int r  = row0 + rl;
            float S1 = s_sum[rl][0] + s_sum[rl][1];
            float S2 = s_sq [rl][0] + s_sq [rl][1];
            float mean = S1 * (1.0f / 192.0f);
            float var  = S2 * (1.0f / 192.0f) - mean * mean;
            float rstd = rsqrtf(var + 1e-5f);
#pragma unroll
            for (int ni = 0; ni < 12; ni++) {
                int col = wn * 96 + ni * 8 + tg * 2;
                float v0 = acc[mi][ni][hh*2], v1 = acc[mi][ni][hh*2 + 1];
                *(float2*)(g_x2 + (size_t)r * 192 + col) = make_float2(v0, v1);
                float n0 = (v0 - mean) * rstd * gam[col]     + bet[col];
                float n1 = (v1 - mean) * rstd * gam[col + 1] + bet[col + 1];
                *(__nv_bfloat162*)(g_h + (size_t)r * 192 + col) =
                    __floats2bfloat162_rn(n0, n1);
            }
        }
    }
}

// ---------------- host launcher ----------------
extern "C" void kernel_launch(void* const* d_in, const int* in_sizes, int n_in,
                              void* d_out, int out_size)
{
    const float* x      = (const float*)d_in[0];
    const float* ln1_g  = (const float*)d_in[1];
    const float* ln1_b  = (const float*)d_in[2];
    const float* qkv_w  = (const float*)d_in[3];
    const float* qkv_b  = (const float*)d_in[4];
    const float* btab   = (const float*)d_in[5];
    const float* proj_w = (const float*)d_in[6];
    const float* proj_b = (const float*)d_in[7];
    const float* ln2_g  = (const float*)d_in[8];
    const float* ln2_b  = (const float*)d_in[9];
    const float* mlp_w1 = (const float*)d_in[10];
    const float* mlp_b1 = (const float*)d_in[11];
    const float* mlp_w2 = (const float*)d_in[12];
    const float* mlp_b2 = (const float*)d_in[13];
    const int*   rel_idx= (const int*)d_in[14];
    float*       out    = (float*)d_out;

    bf16 *p_h, *p_qkv, *p_attn, *p_hid;
    float *p_x2;
    bf16 *p_qkv_wt, *p_proj_wt, *p_w1t, *p_w2t;
    cudaGetSymbolAddress((void**)&p_h,    g_h);
    cudaGetSymbolAddress((void**)&p_qkv,  g_qkv);
    cudaGetSymbolAddress((void**)&p_attn, g_attn);
    cudaGetSymbolAddress((void**)&p_x2,   g_x2);
    cudaGetSymbolAddress((void**)&p_hid,  g_hid);
    cudaGetSymbolAddress((void**)&p_qkv_wt,  g_qkv_wt);
    cudaGetSymbolAddress((void**)&p_proj_wt, g_proj_wt);
    cudaGetSymbolAddress((void**)&p_w1t,  g_w1t);
    cudaGetSymbolAddress((void**)&p_w2t,  g_w2t);

    cudaFuncSetAttribute(tc_gemm<0>, cudaFuncAttributeMaxDynamicSharedMemorySize, GEMM_SMEM);
    cudaFuncSetAttribute(tc_gemm<1>, cudaFuncAttributeMaxDynamicSharedMemorySize, GEMM_SMEM);
    cudaFuncSetAttribute(tc_gemm<3>, cudaFuncAttributeMaxDynamicSharedMemorySize, GEMM_SMEM);
    cudaFuncSetAttribute(proj_ln2_kernel, cudaFuncAttributeMaxDynamicSharedMemorySize, PROJ_SMEM);

    transpose_all_kernel<<<432, dim3(32, 8)>>>(qkv_w, proj_w, mlp_w1, mlp_w2,
                                               p_qkv_wt, p_proj_wt, p_w1t, p_w2t);

    gather_ln1_kernel<<<NTOK_TOTAL / 8, 256>>>(x, ln1_g, ln1_b);

    const int Mb = NTOK_TOTAL / 128;  // 1008
    // QKV: [T,192] @ [192,576]
    tc_gemm<0><<<dim3(6, Mb), 256, GEMM_SMEM>>>(p_h, p_qkv_wt, qkv_b, nullptr, p_qkv, 576, 192);
    // attention
    attn_kernel<<<NWIN, 192>>>(btab, rel_idx);
    // proj + residual(from x) + LN2 -> g_x2 (fp32) and g_h (bf16)
    proj_ln2_kernel<<<Mb, 256, PROJ_SMEM>>>(p_attn, p_proj_wt, proj_b, x, ln2_g, ln2_b);
    // MLP1 + gelu
    tc_gemm<1><<<dim3(8, Mb), 256, GEMM_SMEM>>>(p_h, p_w1t, mlp_b1, nullptr, p_hid, 768, 192);
    // MLP2 + residual + scatter
    tc_gemm<3><<<dim3(2, Mb), 256, GEMM_SMEM>>>(p_hid, p_w2t, mlp_b2, p_x2, out, 192, 768);
}

// round 6
// speedup vs baseline: 3.4303x; 1.0005x over previous
#include <cuda_runtime.h>
#include <cuda_bf16.h>
#include <math.h>
#include <stdint.h>

typedef __nv_bfloat16 bf16;

// ---------------- problem constants ----------------
#define NTOK_TOTAL 129024   // 5376 windows * 24 tokens
#define NWIN       5376
#define HEADS      6

// ---------------- scratch (device globals) ----------------
__device__ float g_x2  [(size_t)NTOK_TOTAL * 192];   // trunk after proj (fp32)
__device__ bf16  g_h   [(size_t)NTOK_TOTAL * 192];   // LN out (bf16, GEMM A)
__device__ bf16  g_qkv [(size_t)NTOK_TOTAL * 576];
__device__ bf16  g_attn[(size_t)NTOK_TOTAL * 192];
__device__ bf16  g_hid [(size_t)NTOK_TOTAL * 768];
__device__ float g_bias6[HEADS * 576];               // bias[h][n][m], window-invariant
// pre-transposed bf16 weights (K-major: Wt[N][K])
__device__ bf16 g_qkv_wt [576 * 192];
__device__ bf16 g_proj_wt[192 * 192];
__device__ bf16 g_w1t    [768 * 192];
__device__ bf16 g_w2t    [192 * 768];

// ---------------- helpers ----------------
__device__ __forceinline__ size_t token_src_offset(int t) {
    int wi = t / 24, n = t % 24;
    int i3 = n / 12, j3 = (n >> 1) % 6, k3 = n & 1;
    int d0 = wi % 7;  int r = wi / 7;
    int w0 = r % 16;  r /= 16;
    int h0 = r % 24;  int b0 = r / 24;
    return ((((size_t)b0 * 48 + (h0 * 2 + i3)) * 96 + (w0 * 6 + j3)) * 14
            + (d0 * 2 + k3)) * 192;
}
__device__ __forceinline__ float warp_sum(float v) {
#pragma unroll
    for (int o = 16; o; o >>= 1) v += __shfl_xor_sync(0xffffffffu, v, o);
    return v;
}
__device__ __forceinline__ float warp_max(float v) {
#pragma unroll
    for (int o = 16; o; o >>= 1) v = fmaxf(v, __shfl_xor_sync(0xffffffffu, v, o));
    return v;
}
__device__ __forceinline__ uint32_t smem_u32(const void* p) {
    uint32_t a;
    asm("{ .reg .u64 t; cvta.to.shared.u64 t, %1; cvt.u32.u64 %0, t; }" : "=r"(a) : "l"(p));
    return a;
}
__device__ __forceinline__ void cp16(uint32_t dst, const void* src) {
    asm volatile("cp.async.cg.shared.global [%0], [%1], 16;" :: "r"(dst), "l"(src));
}
#define CP_COMMIT() asm volatile("cp.async.commit_group;" ::: "memory")
#define CP_WAIT(n)  asm volatile("cp.async.wait_group %0;" :: "n"(n) : "memory")

__device__ __forceinline__ void ldsm_x4(uint32_t* r, uint32_t a) {
    asm volatile("ldmatrix.sync.aligned.m8n8.x4.shared.b16 {%0,%1,%2,%3}, [%4];"
                 : "=r"(r[0]), "=r"(r[1]), "=r"(r[2]), "=r"(r[3]) : "r"(a));
}
__device__ __forceinline__ void mma_bf16(float* d, const uint32_t* a,
                                         const uint32_t* b, const float* c) {
    asm volatile(
        "mma.sync.aligned.m16n8k16.row.col.f32.bf16.bf16.f32 "
        "{%0,%1,%2,%3}, {%4,%5,%6,%7}, {%8,%9}, {%10,%11,%12,%13};"
        : "=f"(d[0]), "=f"(d[1]), "=f"(d[2]), "=f"(d[3])
        : "r"(a[0]), "r"(a[1]), "r"(a[2]), "r"(a[3]),
          "r"(b[0]), "r"(b[1]),
          "f"(c[0]), "f"(c[1]), "f"(c[2]), "f"(c[3]));
}

// ---------------- one-shot weight transpose (all 4 weights) ----------------
__global__ void transpose_all_kernel(
    const float* __restrict__ qkv_w, const float* __restrict__ proj_w,
    const float* __restrict__ w1, const float* __restrict__ w2,
    bf16* __restrict__ qkv_wt, bf16* __restrict__ proj_wt,
    bf16* __restrict__ w1t, bf16* __restrict__ w2t)
{
    __shared__ float t[32][33];
    int bid = blockIdx.x;
    const float* W; bf16* Wt; int K, N, loc;
    if (bid < 108)      { W = qkv_w;  Wt = qkv_wt;  K = 192; N = 576; loc = bid; }
    else if (bid < 144) { W = proj_w; Wt = proj_wt; K = 192; N = 192; loc = bid - 108; }
    else if (bid < 288) { W = w1;     Wt = w1t;     K = 192; N = 768; loc = bid - 144; }
    else                { W = w2;     Wt = w2t;     K = 768; N = 192; loc = bid - 288; }
    int Kt = K / 32;
    int kb = (loc % Kt) * 32, nb = (loc / Kt) * 32;
    int x = threadIdx.x, y = threadIdx.y;
#pragma unroll
    for (int j = 0; j < 32; j += 8) t[y + j][x] = W[(size_t)(kb + y + j) * N + nb + x];
    __syncthreads();
#pragma unroll
    for (int j = 0; j < 32; j += 8)
        Wt[(size_t)(nb + y + j) * K + kb + x] = __float2bfloat16(t[x][y + j]);
}

// ---------------- bias precompute: bias6[h*576 + n*24 + m] ----------------
__global__ void bias_precompute_kernel(const float* __restrict__ bias_table,
                                       const int* __restrict__ rel_index)
{
    int h = blockIdx.x, idx = threadIdx.x;   // idx = n*24 + m
    if (idx < 576)
        g_bias6[h * 576 + idx] = bias_table[rel_index[idx] * HEADS + h];
}

// ---------------- gather + LN1 ----------------
__global__ __launch_bounds__(256) void gather_ln1_kernel(
    const float* __restrict__ x, const float* __restrict__ gam, const float* __restrict__ bet)
{
    int t = blockIdx.x * 8 + (threadIdx.x >> 5);
    int lane = threadIdx.x & 31;
    size_t src = token_src_offset(t);
    float v[6]; float s = 0.f;
#pragma unroll
    for (int q = 0; q < 6; q++) { v[q] = x[src + lane + q * 32]; s += v[q]; }
    float mean = warp_sum(s) * (1.0f / 192.0f);
    float vs = 0.f;
#pragma unroll
    for (int q = 0; q < 6; q++) { float d = v[q] - mean; vs += d * d; }
    float rstd = rsqrtf(warp_sum(vs) * (1.0f / 192.0f) + 1e-5f);
    size_t dst = (size_t)t * 192;
#pragma unroll
    for (int q = 0; q < 6; q++) {
        int c = lane + q * 32;
        g_h[dst + c] = __float2bfloat16((v[q] - mean) * rstd * gam[c] + bet[c]);
    }
}

// ---------------- attention: warp-independent, precomputed bias -------------
__global__ __launch_bounds__(192) void attn_kernel()
{
    __shared__ float q_s[HEADS][24][32];   // reused for P
    __shared__ float v_s[HEADS][24][33];
    const int wi = blockIdx.x;
    const int h = threadIdx.x >> 5, lane = threadIdx.x & 31;
    const bf16* base = g_qkv + (size_t)wi * 24 * 576;
    const float* bias = g_bias6 + h * 576;

#pragma unroll
    for (int n = 0; n < 24; n++) {
        q_s[h][n][lane] = __bfloat162float(base[n * 576 +       h * 32 + lane]);
        v_s[h][n][lane] = __bfloat162float(base[n * 576 + 384 + h * 32 + lane]);
    }
    float kr[32];
    if (lane < 24) {
        const bf16* kp = base + lane * 576 + 192 + h * 32;
#pragma unroll
        for (int d = 0; d < 32; d += 2) {
            __nv_bfloat162 k2 = *(const __nv_bfloat162*)(kp + d);
            kr[d] = __bfloat162float(k2.x); kr[d + 1] = __bfloat162float(k2.y);
        }
    }
    __syncwarp();

    const float scale = 0.17677669529663687f;
    float s[24];
    if (lane < 24) {
#pragma unroll 4
        for (int n = 0; n < 24; n++) {
            float a = 0.f;
#pragma unroll
            for (int d = 0; d < 32; d += 4) {
                float4 q4 = *(const float4*)&q_s[h][n][d];
                a = fmaf(q4.x, kr[d], a); a = fmaf(q4.y, kr[d+1], a);
                a = fmaf(q4.z, kr[d+2], a); a = fmaf(q4.w, kr[d+3], a);
            }
            s[n] = a * scale + bias[n * 24 + lane];
        }
    } else {
#pragma unroll
        for (int n = 0; n < 24; n++) s[n] = -1e30f;
    }
    __syncwarp();
#pragma unroll 4
    for (int n = 0; n < 24; n++) {
        float mx = warp_max(s[n]);
        float e = (lane < 24) ? __expf(s[n] - mx) : 0.f;
        float sm = warp_sum(e);
        if (lane < 24) q_s[h][n][lane] = e / sm;
    }
    __syncwarp();
    float vcol[24];
#pragma unroll
    for (int m = 0; m < 24; m++) vcol[m] = v_s[h][m][lane];
    bf16* ob = g_attn + (size_t)wi * 24 * 192 + h * 32 + lane;
#pragma unroll 4
    for (int n = 0; n < 24; n++) {
        float a = 0.f;
#pragma unroll
        for (int m4 = 0; m4 < 24; m4 += 4) {
            float4 p4 = *(const float4*)&q_s[h][n][m4];
            a = fmaf(p4.x, vcol[m4], a); a = fmaf(p4.y, vcol[m4+1], a);
            a = fmaf(p4.z, vcol[m4+2], a); a = fmaf(p4.w, vcol[m4+3], a);
        }
        ob[n * 192] = __float2bfloat16(a);
    }
}

// ======================= generic bf16 GEMM (BN=96) ==========================
#define GEMM_SMEM (3 * (128 + 96) * 40 * 2)
template <int EPI>
__global__ __launch_bounds__(256) void tc_gemm(
    const bf16* __restrict__ A, const bf16* __restrict__ Bt,
    const float* __restrict__ bias, const float* __restrict__ res,
    void* __restrict__ Cc, int N, int K)
{
    constexpr int LDA = 40;
    constexpr int ASZ = 128 * LDA, BSZ = 96 * LDA;
    extern __shared__ bf16 smem[];
    bf16* Asb = smem;
    bf16* Bsb = smem + 3 * ASZ;

    const int tid  = threadIdx.x;
    const int lane = tid & 31;
    const int wid  = tid >> 5;
    const int wm   = wid & 3;
    const int wn   = wid >> 2;
    const int col0 = blockIdx.x * 96;
    const int row0 = blockIdx.y * 128;
    const int gq = lane >> 2, tg = lane & 3;

    const uint32_t sAb = smem_u32(Asb), sBb = smem_u32(Bsb);

    float acc[2][6][4];
#pragma unroll
    for (int mi = 0; mi < 2; mi++)
#pragma unroll
        for (int ni = 0; ni < 6; ni++)
#pragma unroll
            for (int j = 0; j < 4; j++) acc[mi][ni][j] = 0.f;

    const int nstages = K / 32;

    auto prefetch = [&](int s, int b) {
        const bf16* Ag = A + (size_t)row0 * K + s * 32;
        const bf16* Bg = Bt + (size_t)col0 * K + s * 32;
        uint32_t sA = sAb + (uint32_t)b * ASZ * 2;
        uint32_t sB = sBb + (uint32_t)b * BSZ * 2;
#pragma unroll
        for (int j = 0; j < 2; j++) {
            int idx = tid + j * 256;
            int r = idx >> 2, c = idx & 3;
            cp16(sA + (uint32_t)(r * 80 + c * 16), Ag + (size_t)r * K + c * 8);
        }
        {
            int r = tid >> 2, c = tid & 3;
            cp16(sB + (uint32_t)(r * 80 + c * 16), Bg + (size_t)r * K + c * 8);
        }
        if (tid < 128) {
            int idx = tid + 256;
            int r = idx >> 2, c = idx & 3;
            cp16(sB + (uint32_t)(r * 80 + c * 16), Bg + (size_t)r * K + c * 8);
        }
        CP_COMMIT();
    };

    prefetch(0, 0);
    prefetch(1, 1);

    for (int s = 0; s < nstages; s++) {
        if (s < nstages - 1) CP_WAIT(1); else CP_WAIT(0);
        __syncthreads();
        if (s + 2 < nstages) prefetch(s + 2, (s + 2) % 3);

        const int b = s % 3;
        const uint32_t sA = sAb + (uint32_t)b * ASZ * 2;
        const uint32_t sB = sBb + (uint32_t)b * BSZ * 2;
#pragma unroll
        for (int kk = 0; kk < 32; kk += 16) {
            uint32_t afr[2][4];
            const int arow = wm * 32 + (lane & 15);
            const int acol = kk + (lane >> 4) * 8;
#pragma unroll
            for (int mi = 0; mi < 2; mi++)
                ldsm_x4(afr[mi], sA + (uint32_t)(((arow + mi * 16) * LDA + acol) * 2));

            uint32_t bfr[6][2];
#pragma unroll
            for (int p = 0; p < 3; p++) {
                const int brow = wn * 48 + p * 16 + (lane & 7) + ((lane >> 4) << 3);
                const int bcol = kk + ((lane >> 3) & 1) * 8;
                uint32_t r4[4];
                ldsm_x4(r4, sB + (uint32_t)((brow * LDA + bcol) * 2));
                bfr[2*p][0] = r4[0]; bfr[2*p][1] = r4[1];
                bfr[2*p+1][0] = r4[2]; bfr[2*p+1][1] = r4[3];
            }
#pragma unroll
            for (int mi = 0; mi < 2; mi++)
#pragma unroll
                for (int ni = 0; ni < 6; ni++)
                    mma_bf16(acc[mi][ni], afr[mi], bfr[ni], acc[mi][ni]);
        }
    }

#pragma unroll
    for (int mi = 0; mi < 2; mi++) {
#pragma unroll
        for (int ni = 0; ni < 6; ni++) {
            int row = row0 + wm * 32 + mi * 16 + gq;
            int col = col0 + wn * 48 + ni * 8 + tg * 2;
            float b0 = bias[col], b1 = bias[col + 1];
#pragma unroll
            for (int hh = 0; hh < 2; hh++) {
                int r = row + hh * 8;
                float v0 = acc[mi][ni][hh * 2]     + b0;
                float v1 = acc[mi][ni][hh * 2 + 1] + b1;
                if (EPI == 1) {
                    v0 = 0.5f * v0 * (1.0f + erff(v0 * 0.70710678118654752f));
                    v1 = 0.5f * v1 * (1.0f + erff(v1 * 0.70710678118654752f));
                }
                if (EPI == 3) {
                    const float* rp = res + (size_t)r * 192 + col;
                    v0 += rp[0]; v1 += rp[1];
                    size_t off = token_src_offset(r) + col;
                    *(float2*)((float*)Cc + off) = make_float2(v0, v1);
                } else {
                    bf16* cp_ = (bf16*)Cc + (size_t)r * N + col;
                    *(__nv_bfloat162*)cp_ = __floats2bfloat162_rn(v0, v1);
                }
            }
        }
    }
}

// ================= proj GEMM (BN=192) + residual(from x) + LN2 ==============
#define PROJ_SMEM (3 * (128 + 192) * 40 * 2)
__global__ __launch_bounds__(256) void proj_ln2_kernel(
    const bf16* __restrict__ A, const bf16* __restrict__ Bt,
    const float* __restrict__ bias, const float* __restrict__ x,
    const float* __restrict__ gam, const float* __restrict__ bet)
{
    constexpr int LDA = 40, K = 192;
    constexpr int ASZ = 128 * LDA, BSZ = 192 * LDA;
    extern __shared__ bf16 smem[];
    bf16* Asb = smem;
    bf16* Bsb = smem + 3 * ASZ;
    __shared__ float s_sum[128][2];
    __shared__ float s_sq [128][2];

    const int tid  = threadIdx.x;
    const int lane = tid & 31;
    const int wid  = tid >> 5;
    const int wm   = wid & 3;
    const int wn   = wid >> 2;
    const int row0 = blockIdx.x * 128;
    const int gq = lane >> 2, tg = lane & 3;

    const uint32_t sAb = smem_u32(Asb), sBb = smem_u32(Bsb);

    float acc[2][12][4];
#pragma unroll
    for (int mi = 0; mi < 2; mi++)
#pragma unroll
        for (int ni = 0; ni < 12; ni++)
#pragma unroll
            for (int j = 0; j < 4; j++) acc[mi][ni][j] = 0.f;

    const int nstages = 6;

    auto prefetch = [&](int s, int b) {
        const bf16* Ag = A + (size_t)row0 * K + s * 32;
        const bf16* Bg = Bt + (size_t)s * 32;
        uint32_t sA = sAb + (uint32_t)b * ASZ * 2;
        uint32_t sB = sBb + (uint32_t)b * BSZ * 2;
#pragma unroll
        for (int j = 0; j < 2; j++) {
            int idx = tid + j * 256;
            int r = idx >> 2, c = idx & 3;
            cp16(sA + (uint32_t)(r * 80 + c * 16), Ag + (size_t)r * K + c * 8);
        }
#pragma unroll
        for (int j = 0; j < 3; j++) {
            int idx = tid + j * 256;
            int r = idx >> 2, c = idx & 3;
            cp16(sB + (uint32_t)(r * 80 + c * 16), Bg + (size_t)r * K + c * 8);
        }
        CP_COMMIT();
    };

    prefetch(0, 0);
    prefetch(1, 1);

    for (int s = 0; s < nstages; s++) {
        if (s < nstages - 1) CP_WAIT(1); else CP_WAIT(0);
        __syncthreads();
        if (s + 2 < nstages) prefetch(s + 2, (s + 2) % 3);

        const int b = s % 3;
        const uint32_t sA = sAb + (uint32_t)b * ASZ * 2;
        const uint32_t sB = sBb + (uint32_t)b * BSZ * 2;
#pragma unroll
        for (int kk = 0; kk < 32; kk += 16) {
            uint32_t afr[2][4];
            const int arow = wm * 32 + (lane & 15);
            const int acol = kk + (lane >> 4) * 8;
#pragma unroll
            for (int mi = 0; mi < 2; mi++)
                ldsm_x4(afr[mi], sA + (uint32_t)(((arow + mi * 16) * LDA + acol) * 2));

            uint32_t bfr[12][2];
#pragma unroll
            for (int p = 0; p < 6; p++) {
                const int brow = wn * 96 + p * 16 + (lane & 7) + ((lane >> 4) << 3);
                const int bcol = kk + ((lane >> 3) & 1) * 8;
                uint32_t r4[4];
                ldsm_x4(r4, sB + (uint32_t)((brow * LDA + bcol) * 2));
                bfr[2*p][0] = r4[0]; bfr[2*p][1] = r4[1];
                bfr[2*p+1][0] = r4[2]; bfr[2*p+1][1] = r4[3];
            }
#pragma unroll
            for (int mi = 0; mi < 2; mi++)
#pragma unroll
                for (int ni = 0; ni < 12; ni++)
                    mma_bf16(acc[mi][ni], afr[mi], bfr[ni], acc[mi][ni]);
        }
    }

#pragma unroll
    for (int mi = 0; mi < 2; mi++) {
#pragma unroll
        for (int hh = 0; hh < 2; hh++) {
            int rl = wm * 32 + mi * 16 + gq + hh * 8;
            int r  = row0 + rl;
            size_t roff = token_src_offset(r);
            float s1 = 0.f, s2 = 0.f;
#pragma unroll
            for (int ni = 0; ni < 12; ni++) {
                int col = wn * 96 + ni * 8 + tg * 2;
                float2 rx = *(const float2*)(x + roff + col);
                float v0 = acc[mi][ni][hh*2]     + bias[col]     + rx.x;
                float v1 = acc[mi][ni][hh*2 + 1] + bias[col + 1] + rx.y;
                acc[mi][ni][hh*2]     = v0;
                acc[mi][ni][hh*2 + 1] = v1;
                s1 += v0 + v1;
                s2 += v0 * v0 + v1 * v1;
            }
            s1 += __shfl_xor_sync(0xffffffffu, s1, 1);
            s1 += __shfl_xor_sync(0xffffffffu, s1, 2);
            s2 += __shfl_xor_sync(0xffffffffu, s2, 1);
            s2 += __shfl_xor_sync(0xffffffffu, s2, 2);
            if (tg == 0) { s_sum[rl][wn] = s1; s_sq[rl][wn] = s2; }
        }
    }
    __syncthreads();
#pragma unroll
    for (int mi = 0; mi < 2; mi++) {
#pragma unroll
        for (int hh = 0; hh < 2; hh++) {
            int rl = wm * 32 + mi * 16 + gq + hh * 8;
            int r  = row0 + rl;
            float S1 = s_sum[rl][0] + s_sum[rl][1];
            float S2 = s_sq [rl][0] + s_sq [rl][1];
            float mean = S1 * (1.0f / 192.0f);
            float var  = S2 * (1.0f / 192.0f) - mean * mean;
            float rstd = rsqrtf(var + 1e-5f);
#pragma unroll
            for (int ni = 0; ni < 12; ni++) {
                int col = wn * 96 + ni * 8 + tg * 2;
                float v0 = acc[mi][ni][hh*2], v1 = acc[mi][ni][hh*2 + 1];
                *(float2*)(g_x2 + (size_t)r * 192 + col) = make_float2(v0, v1);
                float n0 = (v0 - mean) * rstd * gam[col]     + bet[col];
                float n1 = (v1 - mean) * rstd * gam[col + 1] + bet[col + 1];
                *(__nv_bfloat162*)(g_h + (size_t)r * 192 + col) =
                    __floats2bfloat162_rn(n0, n1);
            }
        }
    }
}

// ---------------- host launcher ----------------
extern "C" void kernel_launch(void* const* d_in, const int* in_sizes, int n_in,
                              void* d_out, int out_size)
{
    const float* x      = (const float*)d_in[0];
    const float* ln1_g  = (const float*)d_in[1];
    const float* ln1_b  = (const float*)d_in[2];
    const float* qkv_w  = (const float*)d_in[3];
    const float* qkv_b  = (const float*)d_in[4];
    const float* btab   = (const float*)d_in[5];
    const float* proj_w = (const float*)d_in[6];
    const float* proj_b = (const float*)d_in[7];
    const float* ln2_g  = (const float*)d_in[8];
    const float* ln2_b  = (const float*)d_in[9];
    const float* mlp_w1 = (const float*)d_in[10];
    const float* mlp_b1 = (const float*)d_in[11];
    const float* mlp_w2 = (const float*)d_in[12];
    const float* mlp_b2 = (const float*)d_in[13];
    const int*   rel_idx= (const int*)d_in[14];
    float*       out    = (float*)d_out;

    bf16 *p_h, *p_qkv, *p_attn, *p_hid;
    float *p_x2;
    bf16 *p_qkv_wt, *p_proj_wt, *p_w1t, *p_w2t;
    cudaGetSymbolAddress((void**)&p_h,    g_h);
    cudaGetSymbolAddress((void**)&p_qkv,  g_qkv);
    cudaGetSymbolAddress((void**)&p_attn, g_attn);
    cudaGetSymbolAddress((void**)&p_x2,   g_x2);
    cudaGetSymbolAddress((void**)&p_hid,  g_hid);
    cudaGetSymbolAddress((void**)&p_qkv_wt,  g_qkv_wt);
    cudaGetSymbolAddress((void**)&p_proj_wt, g_proj_wt);
    cudaGetSymbolAddress((void**)&p_w1t,  g_w1t);
    cudaGetSymbolAddress((void**)&p_w2t,  g_w2t);

    cudaFuncSetAttribute(tc_gemm<0>, cudaFuncAttributeMaxDynamicSharedMemorySize, GEMM_SMEM);
    cudaFuncSetAttribute(tc_gemm<1>, cudaFuncAttributeMaxDynamicSharedMemorySize, GEMM_SMEM);
    cudaFuncSetAttribute(tc_gemm<3>, cudaFuncAttributeMaxDynamicSharedMemorySize, GEMM_SMEM);
    cudaFuncSetAttribute(proj_ln2_kernel, cudaFuncAttributeMaxDynamicSharedMemorySize, PROJ_SMEM);

    transpose_all_kernel<<<432, dim3(32, 8)>>>(qkv_w, proj_w, mlp_w1, mlp_w2,
                                               p_qkv_wt, p_proj_wt, p_w1t, p_w2t);
    bias_precompute_kernel<<<HEADS, 576>>>(btab, rel_idx);

    gather_ln1_kernel<<<NTOK_TOTAL / 8, 256>>>(x, ln1_g, ln1_b);

    const int Mb = NTOK_TOTAL / 128;  // 1008
    tc_gemm<0><<<dim3(6, Mb), 256, GEMM_SMEM>>>(p_h, p_qkv_wt, qkv_b, nullptr, p_qkv, 576, 192);
    attn_kernel<<<NWIN, 192>>>();
    proj_ln2_kernel<<<Mb, 256, PROJ_SMEM>>>(p_attn, p_proj_wt, proj_b, x, ln2_g, ln2_b);
    tc_gemm<1><<<dim3(8, Mb), 256, GEMM_SMEM>>>(p_h, p_w1t, mlp_b1, nullptr, p_hid, 768, 192);
    tc_gemm<3><<<dim3(2, Mb), 256, GEMM_SMEM>>>(p_hid, p_w2t, mlp_b2, p_x2, out, 192, 768);
}

// round 7
// speedup vs baseline: 3.5841x; 1.0449x over previous
#include <cuda_runtime.h>
#include <cuda_bf16.h>
#include <math.h>
#include <stdint.h>

typedef __nv_bfloat16 bf16;

// ---------------- problem constants ----------------
#define NTOK_TOTAL 129024   // 5376 windows * 24 tokens
#define NWIN       5376
#define HEADS      6

// ---------------- scratch (device globals) ----------------
__device__ float g_x2  [(size_t)NTOK_TOTAL * 192];   // trunk after proj (fp32)
__device__ bf16  g_h   [(size_t)NTOK_TOTAL * 192];   // LN out (bf16, GEMM A)
// qkv in attention-native layout: [win][head][q|k|v][24][32]
__device__ bf16  g_qkv [(size_t)NTOK_TOTAL * 576];
__device__ bf16  g_attn[(size_t)NTOK_TOTAL * 192];
__device__ bf16  g_hid [(size_t)NTOK_TOTAL * 768];
__device__ float g_bias6[HEADS * 576];               // bias[h][n][m], window-invariant
// pre-transposed bf16 weights (K-major: Wt[N][K])
__device__ bf16 g_qkv_wt [576 * 192];
__device__ bf16 g_proj_wt[192 * 192];
__device__ bf16 g_w1t    [768 * 192];
__device__ bf16 g_w2t    [192 * 768];

// ---------------- helpers ----------------
__device__ __forceinline__ size_t token_src_offset(int t) {
    int wi = t / 24, n = t % 24;
    int i3 = n / 12, j3 = (n >> 1) % 6, k3 = n & 1;
    int d0 = wi % 7;  int r = wi / 7;
    int w0 = r % 16;  r /= 16;
    int h0 = r % 24;  int b0 = r / 24;
    return ((((size_t)b0 * 48 + (h0 * 2 + i3)) * 96 + (w0 * 6 + j3)) * 14
            + (d0 * 2 + k3)) * 192;
}
__device__ __forceinline__ float warp_sum(float v) {
#pragma unroll
    for (int o = 16; o; o >>= 1) v += __shfl_xor_sync(0xffffffffu, v, o);
    return v;
}
__device__ __forceinline__ float warp_max(float v) {
#pragma unroll
    for (int o = 16; o; o >>= 1) v = fmaxf(v, __shfl_xor_sync(0xffffffffu, v, o));
    return v;
}
__device__ __forceinline__ uint32_t smem_u32(const void* p) {
    uint32_t a;
    asm("{ .reg .u64 t; cvta.to.shared.u64 t, %1; cvt.u32.u64 %0, t; }" : "=r"(a) : "l"(p));
    return a;
}
__device__ __forceinline__ void cp16(uint32_t dst, const void* src) {
    asm volatile("cp.async.cg.shared.global [%0], [%1], 16;" :: "r"(dst), "l"(src));
}
#define CP_COMMIT() asm volatile("cp.async.commit_group;" ::: "memory")
#define CP_WAIT(n)  asm volatile("cp.async.wait_group %0;" :: "n"(n) : "memory")

__device__ __forceinline__ void ldsm_x4(uint32_t* r, uint32_t a) {
    asm volatile("ldmatrix.sync.aligned.m8n8.x4.shared.b16 {%0,%1,%2,%3}, [%4];"
                 : "=r"(r[0]), "=r"(r[1]), "=r"(r[2]), "=r"(r[3]) : "r"(a));
}
__device__ __forceinline__ void mma_bf16(float* d, const uint32_t* a,
                                         const uint32_t* b, const float* c) {
    asm volatile(
        "mma.sync.aligned.m16n8k16.row.col.f32.bf16.bf16.f32 "
        "{%0,%1,%2,%3}, {%4,%5,%6,%7}, {%8,%9}, {%10,%11,%12,%13};"
        : "=f"(d[0]), "=f"(d[1]), "=f"(d[2]), "=f"(d[3])
        : "r"(a[0]), "r"(a[1]), "r"(a[2]), "r"(a[3]),
          "r"(b[0]), "r"(b[1]),
          "f"(c[0]), "f"(c[1]), "f"(c[2]), "f"(c[3]));
}
__device__ __forceinline__ float2 bf2f2(uint32_t u) {
    __nv_bfloat162 b = *reinterpret_cast<__nv_bfloat162*>(&u);
    return __bfloat1622float2(b);
}

// ---------------- one-shot weight transpose (all 4 weights) ----------------
__global__ void transpose_all_kernel(
    const float* __restrict__ qkv_w, const float* __restrict__ proj_w,
    const float* __restrict__ w1, const float* __restrict__ w2,
    bf16* __restrict__ qkv_wt, bf16* __restrict__ proj_wt,
    bf16* __restrict__ w1t, bf16* __restrict__ w2t)
{
    __shared__ float t[32][33];
    int bid = blockIdx.x;
    const float* W; bf16* Wt; int K, N, loc;
    if (bid < 108)      { W = qkv_w;  Wt = qkv_wt;  K = 192; N = 576; loc = bid; }
    else if (bid < 144) { W = proj_w; Wt = proj_wt; K = 192; N = 192; loc = bid - 108; }
    else if (bid < 288) { W = w1;     Wt = w1t;     K = 192; N = 768; loc = bid - 144; }
    else                { W = w2;     Wt = w2t;     K = 768; N = 192; loc = bid - 288; }
    int Kt = K / 32;
    int kb = (loc % Kt) * 32, nb = (loc / Kt) * 32;
    int x = threadIdx.x, y = threadIdx.y;
#pragma unroll
    for (int j = 0; j < 32; j += 8) t[y + j][x] = W[(size_t)(kb + y + j) * N + nb + x];
    __syncthreads();
#pragma unroll
    for (int j = 0; j < 32; j += 8)
        Wt[(size_t)(nb + y + j) * K + kb + x] = __float2bfloat16(t[x][y + j]);
}

// ---------------- bias precompute: bias6[h*576 + n*24 + m] ----------------
__global__ void bias_precompute_kernel(const float* __restrict__ bias_table,
                                       const int* __restrict__ rel_index)
{
    int h = blockIdx.x, idx = threadIdx.x;
    if (idx < 576)
        g_bias6[h * 576 + idx] = bias_table[rel_index[idx] * HEADS + h];
}

// ---------------- gather + LN1 ----------------
__global__ __launch_bounds__(256) void gather_ln1_kernel(
    const float* __restrict__ x, const float* __restrict__ gam, const float* __restrict__ bet)
{
    int t = blockIdx.x * 8 + (threadIdx.x >> 5);
    int lane = threadIdx.x & 31;
    size_t src = token_src_offset(t);
    float v[6]; float s = 0.f;
#pragma unroll
    for (int q = 0; q < 6; q++) { v[q] = x[src + lane + q * 32]; s += v[q]; }
    float mean = warp_sum(s) * (1.0f / 192.0f);
    float vs = 0.f;
#pragma unroll
    for (int q = 0; q < 6; q++) { float d = v[q] - mean; vs += d * d; }
    float rstd = rsqrtf(warp_sum(vs) * (1.0f / 192.0f) + 1e-5f);
    size_t dst = (size_t)t * 192;
#pragma unroll
    for (int q = 0; q < 6; q++) {
        int c = lane + q * 32;
        g_h[dst + c] = __float2bfloat16((v[q] - mean) * rstd * gam[c] + bet[c]);
    }
}

// ---------------- attention: one warp per (win,head), coalesced loads ------
__global__ __launch_bounds__(256) void attn_kernel()
{
    __shared__ float q_s[8][768];   // [n*32 + d], reused for P[n][m] (24x24 @ stride 32)
    __shared__ float v_s[8][768];
    const int w = threadIdx.x >> 5, lane = threadIdx.x & 31;
    const int pair = blockIdx.x * 8 + w;
    const int wi = pair / 6, h = pair % 6;
    const bf16* base = g_qkv + (size_t)pair * 2304;   // [q 768 | k 768 | v 768]
    const float* bias = g_bias6 + h * 576;

    // q, v: contiguous 1536B each -> fully coalesced uint4 loads, cvt to fp32 smem
#pragma unroll
    for (int j = 0; j < 3; j++) {
        int idx = (lane + j * 32) * 8;
        uint4 uq = *(const uint4*)(base + idx);
        uint4 uv = *(const uint4*)(base + 1536 + idx);
        float2 f;
        f = bf2f2(uq.x); q_s[w][idx+0] = f.x; q_s[w][idx+1] = f.y;
        f = bf2f2(uq.y); q_s[w][idx+2] = f.x; q_s[w][idx+3] = f.y;
        f = bf2f2(uq.z); q_s[w][idx+4] = f.x; q_s[w][idx+5] = f.y;
        f = bf2f2(uq.w); q_s[w][idx+6] = f.x; q_s[w][idx+7] = f.y;
        f = bf2f2(uv.x); v_s[w][idx+0] = f.x; v_s[w][idx+1] = f.y;
        f = bf2f2(uv.y); v_s[w][idx+2] = f.x; v_s[w][idx+3] = f.y;
        f = bf2f2(uv.z); v_s[w][idx+4] = f.x; v_s[w][idx+5] = f.y;
        f = bf2f2(uv.w); v_s[w][idx+6] = f.x; v_s[w][idx+7] = f.y;
    }
    // k row m -> lane m registers (contiguous 1536B region across lanes)
    float kr[32];
    if (lane < 24) {
        const bf16* kp = base + 768 + lane * 32;
#pragma unroll
        for (int d = 0; d < 32; d += 8) {
            uint4 u = *(const uint4*)(kp + d);
            float2 f;
            f = bf2f2(u.x); kr[d+0] = f.x; kr[d+1] = f.y;
            f = bf2f2(u.y); kr[d+2] = f.x; kr[d+3] = f.y;
            f = bf2f2(u.z); kr[d+4] = f.x; kr[d+5] = f.y;
            f = bf2f2(u.w); kr[d+6] = f.x; kr[d+7] = f.y;
        }
    }
    __syncwarp();

    const float scale = 0.17677669529663687f;
    float s[24];
    if (lane < 24) {
#pragma unroll 4
        for (int n = 0; n < 24; n++) {
            float a = 0.f;
#pragma unroll
            for (int d = 0; d < 32; d += 4) {
                float4 q4 = *(const float4*)&q_s[w][n * 32 + d];
                a = fmaf(q4.x, kr[d], a); a = fmaf(q4.y, kr[d+1], a);
                a = fmaf(q4.z, kr[d+2], a); a = fmaf(q4.w, kr[d+3], a);
            }
            s[n] = a * scale + bias[n * 24 + lane];
        }
    } else {
#pragma unroll
        for (int n = 0; n < 24; n++) s[n] = -1e30f;
    }
    __syncwarp();
    // softmax over m (lanes); write P into q_s (q no longer needed)
#pragma unroll 4
    for (int n = 0; n < 24; n++) {
        float mx = warp_max(s[n]);
        float e = (lane < 24) ? __expf(s[n] - mx) : 0.f;
        float sm = warp_sum(e);
        if (lane < 24) q_s[w][n * 32 + lane] = e / sm;
    }
    __syncwarp();
    float vcol[24];
#pragma unroll
    for (int m = 0; m < 24; m++) vcol[m] = v_s[w][m * 32 + lane];
    bf16* ob = g_attn + ((size_t)wi * 24) * 192 + h * 32 + lane;
#pragma unroll 4
    for (int n = 0; n < 24; n++) {
        float a = 0.f;
#pragma unroll
        for (int m4 = 0; m4 < 24; m4 += 4) {
            float4 p4 = *(const float4*)&q_s[w][n * 32 + m4];
            a = fmaf(p4.x, vcol[m4], a); a = fmaf(p4.y, vcol[m4+1], a);
            a = fmaf(p4.z, vcol[m4+2], a); a = fmaf(p4.w, vcol[m4+3], a);
        }
        ob[n * 192] = __float2bfloat16(a);
    }
}

// ======================= generic bf16 GEMM (BN=96) ==========================
// EPI: 0 bias->bf16 scatter to qkv layout, 1 bias+gelu->bf16,
//      3 bias+res+scatter->fp32 output
#define GEMM_SMEM (3 * (128 + 96) * 40 * 2)
template <int EPI>
__global__ __launch_bounds__(256) void tc_gemm(
    const bf16* __restrict__ A, const bf16* __restrict__ Bt,
    const float* __restrict__ bias, const float* __restrict__ res,
    void* __restrict__ Cc, int N, int K)
{
    constexpr int LDA = 40;
    constexpr int ASZ = 128 * LDA, BSZ = 96 * LDA;
    extern __shared__ bf16 smem[];
    bf16* Asb = smem;
    bf16* Bsb = smem + 3 * ASZ;

    const int tid  = threadIdx.x;
    const int lane = tid & 31;
    const int wid  = tid >> 5;
    const int wm   = wid & 3;
    const int wn   = wid >> 2;
    const int col0 = blockIdx.x * 96;
    const int row0 = blockIdx.y * 128;
    const int gq = lane >> 2, tg = lane & 3;

    const uint32_t sAb = smem_u32(Asb), sBb = smem_u32(Bsb);

    float acc[2][6][4];
#pragma unroll
    for (int mi = 0; mi < 2; mi++)
#pragma unroll
        for (int ni = 0; ni < 6; ni++)
#pragma unroll
            for (int j = 0; j < 4; j++) acc[mi][ni][j] = 0.f;

    const int nstages = K / 32;

    auto prefetch = [&](int s, int b) {
        const bf16* Ag = A + (size_t)row0 * K + s * 32;
        const bf16* Bg = Bt + (size_t)col0 * K + s * 32;
        uint32_t sA = sAb + (uint32_t)b * ASZ * 2;
        uint32_t sB = sBb + (uint32_t)b * BSZ * 2;
#pragma unroll
        for (int j = 0; j < 2; j++) {
            int idx = tid + j * 256;
            int r = idx >> 2, c = idx & 3;
            cp16(sA + (uint32_t)(r * 80 + c * 16), Ag + (size_t)r * K + c * 8);
        }
        {
            int r = tid >> 2, c = tid & 3;
            cp16(sB + (uint32_t)(r * 80 + c * 16), Bg + (size_t)r * K + c * 8);
        }
        if (tid < 128) {
            int idx = tid + 256;
            int r = idx >> 2, c = idx & 3;
            cp16(sB + (uint32_t)(r * 80 + c * 16), Bg + (size_t)r * K + c * 8);
        }
        CP_COMMIT();
    };

    prefetch(0, 0);
    prefetch(1, 1);

    for (int s = 0; s < nstages; s++) {
        if (s < nstages - 1) CP_WAIT(1); else CP_WAIT(0);
        __syncthreads();
        if (s + 2 < nstages) prefetch(s + 2, (s + 2) % 3);

        const int b = s % 3;
        const uint32_t sA = sAb + (uint32_t)b * ASZ * 2;
        const uint32_t sB = sBb + (uint32_t)b * BSZ * 2;
#pragma unroll
        for (int kk = 0; kk < 32; kk += 16) {
            uint32_t afr[2][4];
            const int arow = wm * 32 + (lane & 15);
            const int acol = kk + (lane >> 4) * 8;
#pragma unroll
            for (int mi = 0; mi < 2; mi++)
                ldsm_x4(afr[mi], sA + (uint32_t)(((arow + mi * 16) * LDA + acol) * 2));

            uint32_t bfr[6][2];
#pragma unroll
            for (int p = 0; p < 3; p++) {
                const int brow = wn * 48 + p * 16 + (lane & 7) + ((lane >> 4) << 3);
                const int bcol = kk + ((lane >> 3) & 1) * 8;
                uint32_t r4[4];
                ldsm_x4(r4, sB + (uint32_t)((brow * LDA + bcol) * 2));
                bfr[2*p][0] = r4[0]; bfr[2*p][1] = r4[1];
                bfr[2*p+1][0] = r4[2]; bfr[2*p+1][1] = r4[3];
            }
#pragma unroll
            for (int mi = 0; mi < 2; mi++)
#pragma unroll
                for (int ni = 0; ni < 6; ni++)
                    mma_bf16(acc[mi][ni], afr[mi], bfr[ni], acc[mi][ni]);
        }
    }

#pragma unroll
    for (int mi = 0; mi < 2; mi++) {
#pragma unroll
        for (int ni = 0; ni < 6; ni++) {
            int row = row0 + wm * 32 + mi * 16 + gq;
            int col = col0 + wn * 48 + ni * 8 + tg * 2;
            float b0 = bias[col], b1 = bias[col + 1];
#pragma unroll
            for (int hh = 0; hh < 2; hh++) {
                int r = row + hh * 8;
                float v0 = acc[mi][ni][hh * 2]     + b0;
                float v1 = acc[mi][ni][hh * 2 + 1] + b1;
                if (EPI == 1) {
                    v0 = 0.5f * v0 * (1.0f + erff(v0 * 0.70710678118654752f));
                    v1 = 0.5f * v1 * (1.0f + erff(v1 * 0.70710678118654752f));
                }
                if (EPI == 0) {
                    // scatter into [win][head][q|k|v][24][32] layout
                    int wi2 = r / 24, n2 = r - wi2 * 24;
                    int which = col / 192;
                    int rem = col - which * 192;
                    int h2 = rem >> 5, d2 = rem & 31;
                    bf16* cp_ = (bf16*)Cc +
                        ((((size_t)wi2 * 6 + h2) * 3 + which) * 768 + n2 * 32 + d2);
                    *(__nv_bfloat162*)cp_ = __floats2bfloat162_rn(v0, v1);
                } else if (EPI == 3) {
                    const float* rp = res + (size_t)r * 192 + col;
                    v0 += rp[0]; v1 += rp[1];
                    size_t off = token_src_offset(r) + col;
                    *(float2*)((float*)Cc + off) = make_float2(v0, v1);
                } else {
                    bf16* cp_ = (bf16*)Cc + (size_t)r * N + col;
                    *(__nv_bfloat162*)cp_ = __floats2bfloat162_rn(v0, v1);
                }
            }
        }
    }
}

// ================= proj GEMM (BN=192) + residual(from x) + LN2 ==============
#define PROJ_SMEM (3 * (128 + 192) * 40 * 2)
__global__ __launch_bounds__(256) void proj_ln2_kernel(
    const bf16* __restrict__ A, const bf16* __restrict__ Bt,
    const float* __restrict__ bias, const float* __restrict__ x,
    const float* __restrict__ gam, const float* __restrict__ bet)
{
    constexpr int LDA = 40, K = 192;
    constexpr int ASZ = 128 * LDA, BSZ = 192 * LDA;
    extern __shared__ bf16 smem[];
    bf16* Asb = smem;
    bf16* Bsb = smem + 3 * ASZ;
    __shared__ float s_sum[128][2];
    __shared__ float s_sq [128][2];

    const int tid  = threadIdx.x;
    const int lane = tid & 31;
    const int wid  = tid >> 5;
    const int wm   = wid & 3;
    const int wn   = wid >> 2;
    const int row0 = blockIdx.x * 128;
    const int gq = lane >> 2, tg = lane & 3;

    const uint32_t sAb = smem_u32(Asb), sBb = smem_u32(Bsb);

    float acc[2][12][4];
#pragma unroll
    for (int mi = 0; mi < 2; mi++)
#pragma unroll
        for (int ni = 0; ni < 12; ni++)
#pragma unroll
            for (int j = 0; j < 4; j++) acc[mi][ni][j] = 0.f;

    const int nstages = 6;

    auto prefetch = [&](int s, int b) {
        const bf16* Ag = A + (size_t)row0 * K + s * 32;
        const bf16* Bg = Bt + (size_t)s * 32;
        uint32_t sA = sAb + (uint32_t)b * ASZ * 2;
        uint32_t sB = sBb + (uint32_t)b * BSZ * 2;
#pragma unroll
        for (int j = 0; j < 2; j++) {
            int idx = tid + j * 256;
            int r = idx >> 2, c = idx & 3;
            cp16(sA + (uint32_t)(r * 80 + c * 16), Ag + (size_t)r * K + c * 8);
        }
#pragma unroll
        for (int j = 0; j < 3; j++) {
            int idx = tid + j * 256;
            int r = idx >> 2, c = idx & 3;
            cp16(sB + (uint32_t)(r * 80 + c * 16), Bg + (size_t)r * K + c * 8);
        }
        CP_COMMIT();
    };

    prefetch(0, 0);
    prefetch(1, 1);

    for (int s = 0; s < nstages; s++) {
        if (s < nstages - 1) CP_WAIT(1); else CP_WAIT(0);
        __syncthreads();
        if (s + 2 < nstages) prefetch(s + 2, (s + 2) % 3);

        const int b = s % 3;
        const uint32_t sA = sAb + (uint32_t)b * ASZ * 2;
        const uint32_t sB = sBb + (uint32_t)b * BSZ * 2;
#pragma unroll
        for (int kk = 0; kk < 32; kk += 16) {
            uint32_t afr[2][4];
            const int arow = wm * 32 + (lane & 15);
            const int acol = kk + (lane >> 4) * 8;
#pragma unroll
            for (int mi = 0; mi < 2; mi++)
                ldsm_x4(afr[mi], sA + (uint32_t)(((arow + mi * 16) * LDA + acol) * 2));

            uint32_t bfr[12][2];
#pragma unroll
            for (int p = 0; p < 6; p++) {
                const int brow = wn * 96 + p * 16 + (lane & 7) + ((lane >> 4) << 3);
                const int bcol = kk + ((lane >> 3) & 1) * 8;
                uint32_t r4[4];
                ldsm_x4(r4, sB + (uint32_t)((brow * LDA + bcol) * 2));
                bfr[2*p][0] = r4[0]; bfr[2*p][1] = r4[1];
                bfr[2*p+1][0] = r4[2]; bfr[2*p+1][1] = r4[3];
            }
#pragma unroll
            for (int mi = 0; mi < 2; mi++)
#pragma unroll
                for (int ni = 0; ni < 12; ni++)
                    mma_bf16(acc[mi][ni], afr[mi], bfr[ni], acc[mi][ni]);
        }
    }

#pragma unroll
    for (int mi = 0; mi < 2; mi++) {
#pragma unroll
        for (int hh = 0; hh < 2; hh++) {
            int rl = wm * 32 + mi * 16 + gq + hh * 8;
            int r  = row0 + rl;
            size_t roff = token_src_offset(r);
            float s1 = 0.f, s2 = 0.f;
#pragma unroll
            for (int ni = 0; ni < 12; ni++) {
                int col = wn * 96 + ni * 8 + tg * 2;
                float2 rx = *(const float2*)(x + roff + col);
                float v0 = acc[mi][ni][hh*2]     + bias[col]     + rx.x;
                float v1 = acc[mi][ni][hh*2 + 1] + bias[col + 1] + rx.y;
                acc[mi][ni][hh*2]     = v0;
                acc[mi][ni][hh*2 + 1] = v1;
                s1 += v0 + v1;
                s2 += v0 * v0 + v1 * v1;
            }
            s1 += __shfl_xor_sync(0xffffffffu, s1, 1);
            s1 += __shfl_xor_sync(0xffffffffu, s1, 2);
            s2 += __shfl_xor_sync(0xffffffffu, s2, 1);
            s2 += __shfl_xor_sync(0xffffffffu, s2, 2);
            if (tg == 0) { s_sum[rl][wn] = s1; s_sq[rl][wn] = s2; }
        }
    }
    __syncthreads();
#pragma unroll
    for (int mi = 0; mi < 2; mi++) {
#pragma unroll
        for (int hh = 0; hh < 2; hh++) {
            int rl = wm * 32 + mi * 16 + gq + hh * 8;
            int r  = row0 + rl;
            float S1 = s_sum[rl][0] + s_sum[rl][1];
            float S2 = s_sq [rl][0] + s_sq [rl][1];
            float mean = S1 * (1.0f / 192.0f);
            float var  = S2 * (1.0f / 192.0f) - mean * mean;
            float rstd = rsqrtf(var + 1e-5f);
#pragma unroll
            for (int ni = 0; ni < 12; ni++) {
                int col = wn * 96 + ni * 8 + tg * 2;
                float v0 = acc[mi][ni][hh*2], v1 = acc[mi][ni][hh*2 + 1];
                *(float2*)(g_x2 + (size_t)r * 192 + col) = make_float2(v0, v1);
                float n0 = (v0 - mean) * rstd * gam[col]     + bet[col];
                float n1 = (v1 - mean) * rstd * gam[col + 1] + bet[col + 1];
                *(__nv_bfloat162*)(g_h + (size_t)r * 192 + col) =
                    __floats2bfloat162_rn(n0, n1);
            }
        }
    }
}

// ---------------- host launcher ----------------
extern "C" void kernel_launch(void* const* d_in, const int* in_sizes, int n_in,
                              void* d_out, int out_size)
{
    const float* x      = (const float*)d_in[0];
    const float* ln1_g  = (const float*)d_in[1];
    const float* ln1_b  = (const float*)d_in[2];
    const float* qkv_w  = (const float*)d_in[3];
    const float* qkv_b  = (const float*)d_in[4];
    const float* btab   = (const float*)d_in[5];
    const float* proj_w = (const float*)d_in[6];
    const float* proj_b = (const float*)d_in[7];
    const float* ln2_g  = (const float*)d_in[8];
    const float* ln2_b  = (const float*)d_in[9];
    const float* mlp_w1 = (const float*)d_in[10];
    const float* mlp_b1 = (const float*)d_in[11];
    const float* mlp_w2 = (const float*)d_in[12];
    const float* mlp_b2 = (const float*)d_in[13];
    const int*   rel_idx= (const int*)d_in[14];
    float*       out    = (float*)d_out;

    bf16 *p_h, *p_qkv, *p_attn, *p_hid;
    float *p_x2;
    bf16 *p_qkv_wt, *p_proj_wt, *p_w1t, *p_w2t;
    cudaGetSymbolAddress((void**)&p_h,    g_h);
    cudaGetSymbolAddress((void**)&p_qkv,  g_qkv);
    cudaGetSymbolAddress((void**)&p_attn, g_attn);
    cudaGetSymbolAddress((void**)&p_x2,   g_x2);
    cudaGetSymbolAddress((void**)&p_hid,  g_hid);
    cudaGetSymbolAddress((void**)&p_qkv_wt,  g_qkv_wt);
    cudaGetSymbolAddress((void**)&p_proj_wt, g_proj_wt);
    cudaGetSymbolAddress((void**)&p_w1t,  g_w1t);
    cudaGetSymbolAddress((void**)&p_w2t,  g_w2t);

    cudaFuncSetAttribute(tc_gemm<0>, cudaFuncAttributeMaxDynamicSharedMemorySize, GEMM_SMEM);
    cudaFuncSetAttribute(tc_gemm<1>, cudaFuncAttributeMaxDynamicSharedMemorySize, GEMM_SMEM);
    cudaFuncSetAttribute(tc_gemm<3>, cudaFuncAttributeMaxDynamicSharedMemorySize, GEMM_SMEM);
    cudaFuncSetAttribute(proj_ln2_kernel, cudaFuncAttributeMaxDynamicSharedMemorySize, PROJ_SMEM);

    transpose_all_kernel<<<432, dim3(32, 8)>>>(qkv_w, proj_w, mlp_w1, mlp_w2,
                                               p_qkv_wt, p_proj_wt, p_w1t, p_w2t);
    bias_precompute_kernel<<<HEADS, 576>>>(btab, rel_idx);

    gather_ln1_kernel<<<NTOK_TOTAL / 8, 256>>>(x, ln1_g, ln1_b);

    const int Mb = NTOK_TOTAL / 128;  // 1008
    tc_gemm<0><<<dim3(6, Mb), 256, GEMM_SMEM>>>(p_h, p_qkv_wt, qkv_b, nullptr, p_qkv, 576, 192);
    attn_kernel<<<NWIN * HEADS / 8, 256>>>();
    proj_ln2_kernel<<<Mb, 256, PROJ_SMEM>>>(p_attn, p_proj_wt, proj_b, x, ln2_g, ln2_b);
    tc_gemm<1><<<dim3(8, Mb), 256, GEMM_SMEM>>>(p_h, p_w1t, mlp_b1, nullptr, p_hid, 768, 192);
    tc_gemm<3><<<dim3(2, Mb), 256, GEMM_SMEM>>>(p_hid, p_w2t, mlp_b2, p_x2, out, 192, 768);
}

// round 9
// speedup vs baseline: 3.7849x; 1.0560x over previous
#include <cuda_runtime.h>
#include <cuda_bf16.h>
#include <math.h>
#include <stdint.h>

typedef __nv_bfloat16 bf16;

// ---------------- problem constants ----------------
#define NTOK_TOTAL 129024   // 5376 windows * 24 tokens
#define NWIN       5376
#define HEADS      6

// ---------------- scratch (device globals) ----------------
__device__ float g_x2  [(size_t)NTOK_TOTAL * 192];   // trunk after proj (fp32)
__device__ bf16  g_h   [(size_t)NTOK_TOTAL * 192];   // LN out (bf16, GEMM A)
// qkv in attention-native layout: [win][head][q|k|v][24][32]
__device__ bf16  g_qkv [(size_t)NTOK_TOTAL * 576];
// attn out in [win][head][24][32] layout
__device__ bf16  g_attn[(size_t)NTOK_TOTAL * 192];
__device__ bf16  g_hid [(size_t)NTOK_TOTAL * 768];
__device__ float g_bias6[HEADS * 576];               // bias[h][m][n] (transposed!)
// pre-transposed bf16 weights (K-major: Wt[N][K])
__device__ bf16 g_qkv_wt [576 * 192];
__device__ bf16 g_proj_wt[192 * 192];
__device__ bf16 g_w1t    [768 * 192];
__device__ bf16 g_w2t    [192 * 768];

// ---------------- helpers ----------------
__device__ __forceinline__ size_t token_src_offset(int t) {
    int wi = t / 24, n = t % 24;
    int i3 = n / 12, j3 = (n >> 1) % 6, k3 = n & 1;
    int d0 = wi % 7;  int r = wi / 7;
    int w0 = r % 16;  r /= 16;
    int h0 = r % 24;  int b0 = r / 24;
    return ((((size_t)b0 * 48 + (h0 * 2 + i3)) * 96 + (w0 * 6 + j3)) * 14
            + (d0 * 2 + k3)) * 192;
}
__device__ __forceinline__ float warp_sum(float v) {
#pragma unroll
    for (int o = 16; o; o >>= 1) v += __shfl_xor_sync(0xffffffffu, v, o);
    return v;
}
__device__ __forceinline__ uint32_t smem_u32(const void* p) {
    uint32_t a;
    asm("{ .reg .u64 t; cvta.to.shared.u64 t, %1; cvt.u32.u64 %0, t; }" : "=r"(a) : "l"(p));
    return a;
}
__device__ __forceinline__ void cp16(uint32_t dst, const void* src) {
    asm volatile("cp.async.cg.shared.global [%0], [%1], 16;" :: "r"(dst), "l"(src));
}
#define CP_COMMIT() asm volatile("cp.async.commit_group;" ::: "memory")
#define CP_WAIT(n)  asm volatile("cp.async.wait_group %0;" :: "n"(n) : "memory")

__device__ __forceinline__ void ldsm_x4(uint32_t* r, uint32_t a) {
    asm volatile("ldmatrix.sync.aligned.m8n8.x4.shared.b16 {%0,%1,%2,%3}, [%4];"
                 : "=r"(r[0]), "=r"(r[1]), "=r"(r[2]), "=r"(r[3]) : "r"(a));
}
__device__ __forceinline__ void mma_bf16(float* d, const uint32_t* a,
                                         const uint32_t* b, const float* c) {
    asm volatile(
        "mma.sync.aligned.m16n8k16.row.col.f32.bf16.bf16.f32 "
        "{%0,%1,%2,%3}, {%4,%5,%6,%7}, {%8,%9}, {%10,%11,%12,%13};"
        : "=f"(d[0]), "=f"(d[1]), "=f"(d[2]), "=f"(d[3])
        : "r"(a[0]), "r"(a[1]), "r"(a[2]), "r"(a[3]),
          "r"(b[0]), "r"(b[1]),
          "f"(c[0]), "f"(c[1]), "f"(c[2]), "f"(c[3]));
}
__device__ __forceinline__ float2 bf2f2(uint32_t u) {
    __nv_bfloat162 b = *reinterpret_cast<__nv_bfloat162*>(&u);
    return __bfloat1622float2(b);
}
__device__ __forceinline__ uint32_t f2bf2u(float lo, float hi) {
    __nv_bfloat162 b = __floats2bfloat162_rn(lo, hi);
    return *reinterpret_cast<uint32_t*>(&b);
}

// ---------------- one-shot weight transpose (all 4 weights) ----------------
__global__ void transpose_all_kernel(
    const float* __restrict__ qkv_w, const float* __restrict__ proj_w,
    const float* __restrict__ w1, const float* __restrict__ w2,
    bf16* __restrict__ qkv_wt, bf16* __restrict__ proj_wt,
    bf16* __restrict__ w1t, bf16* __restrict__ w2t)
{
    __shared__ float t[32][33];
    int bid = blockIdx.x;
    const float* W; bf16* Wt; int K, N, loc;
    if (bid < 108)      { W = qkv_w;  Wt = qkv_wt;  K = 192; N = 576; loc = bid; }
    else if (bid < 144) { W = proj_w; Wt = proj_wt; K = 192; N = 192; loc = bid - 108; }
    else if (bid < 288) { W = w1;     Wt = w1t;     K = 192; N = 768; loc = bid - 144; }
    else                { W = w2;     Wt = w2t;     K = 768; N = 192; loc = bid - 288; }
    int Kt = K / 32;
    int kb = (loc % Kt) * 32, nb = (loc / Kt) * 32;
    int x = threadIdx.x, y = threadIdx.y;
#pragma unroll
    for (int j = 0; j < 32; j += 8) t[y + j][x] = W[(size_t)(kb + y + j) * N + nb + x];
    __syncthreads();
#pragma unroll
    for (int j = 0; j < 32; j += 8)
        Wt[(size_t)(nb + y + j) * K + kb + x] = __float2bfloat16(t[x][y + j]);
}

// ---------------- bias precompute (TRANSPOSED): bias6[h*576 + m*24 + n] -----
__global__ void bias_precompute_kernel(const float* __restrict__ bias_table,
                                       const int* __restrict__ rel_index)
{
    int h = blockIdx.x, idx = threadIdx.x;   // idx = m*24 + n
    if (idx < 576) {
        int m = idx / 24, n = idx - m * 24;
        g_bias6[h * 576 + idx] = bias_table[rel_index[n * 24 + m] * HEADS + h];
    }
}

// ---------------- gather + LN1 ----------------
__global__ __launch_bounds__(256) void gather_ln1_kernel(
    const float* __restrict__ x, const float* __restrict__ gam, const float* __restrict__ bet)
{
    int t = blockIdx.x * 8 + (threadIdx.x >> 5);
    int lane = threadIdx.x & 31;
    size_t src = token_src_offset(t);
    float v[6]; float s = 0.f;
#pragma unroll
    for (int q = 0; q < 6; q++) { v[q] = x[src + lane + q * 32]; s += v[q]; }
    float mean = warp_sum(s) * (1.0f / 192.0f);
    float vs = 0.f;
#pragma unroll
    for (int q = 0; q < 6; q++) { float d = v[q] - mean; vs += d * d; }
    float rstd = rsqrtf(warp_sum(vs) * (1.0f / 192.0f) + 1e-5f);
    size_t dst = (size_t)t * 192;
#pragma unroll
    for (int q = 0; q < 6; q++) {
        int c = lane + q * 32;
        g_h[dst + c] = __float2bfloat16((v[q] - mean) * rstd * gam[c] + bet[c]);
    }
}

// ---------------- attention: lane = query row, shfl-free softmax ------------
__global__ __launch_bounds__(256) void attn_kernel()
{
    __shared__ float k_s[8][768];   // [m*32 + d]
    __shared__ float v_s[8][768];
    const int w = threadIdx.x >> 5, lane = threadIdx.x & 31;
    const int pair = blockIdx.x * 8 + w;
    const int h = pair % 6;
    const bf16* base = g_qkv + (size_t)pair * 2304;   // [q 768 | k 768 | v 768]
    const float* bias = g_bias6 + h * 576;            // [m][n]

    // cooperative coalesced k, v loads -> fp32 smem
#pragma unroll
    for (int j = 0; j < 3; j++) {
        int idx = (lane + j * 32) * 8;
        uint4 uk = *(const uint4*)(base + 768 + idx);
        uint4 uv = *(const uint4*)(base + 1536 + idx);
        float2 f;
        f = bf2f2(uk.x); k_s[w][idx+0] = f.x; k_s[w][idx+1] = f.y;
        f = bf2f2(uk.y); k_s[w][idx+2] = f.x; k_s[w][idx+3] = f.y;
        f = bf2f2(uk.z); k_s[w][idx+4] = f.x; k_s[w][idx+5] = f.y;
        f = bf2f2(uk.w); k_s[w][idx+6] = f.x; k_s[w][idx+7] = f.y;
        f = bf2f2(uv.x); v_s[w][idx+0] = f.x; v_s[w][idx+1] = f.y;
        f = bf2f2(uv.y); v_s[w][idx+2] = f.x; v_s[w][idx+3] = f.y;
        f = bf2f2(uv.z); v_s[w][idx+4] = f.x; v_s[w][idx+5] = f.y;
        f = bf2f2(uv.w); v_s[w][idx+6] = f.x; v_s[w][idx+7] = f.y;
    }
    __syncwarp();

    if (lane < 24) {
        // q row 'lane' -> registers (coalesced: 64B per lane, contiguous)
        float q[32];
        const bf16* qp = base + lane * 32;
#pragma unroll
        for (int d = 0; d < 32; d += 8) {
            uint4 u = *(const uint4*)(qp + d);
            float2 f;
            f = bf2f2(u.x); q[d+0] = f.x; q[d+1] = f.y;
            f = bf2f2(u.y); q[d+2] = f.x; q[d+3] = f.y;
            f = bf2f2(u.z); q[d+4] = f.x; q[d+5] = f.y;
            f = bf2f2(u.w); q[d+6] = f.x; q[d+7] = f.y;
        }

        const float scale = 0.17677669529663687f;  // 32^-0.5
        float p[24];
        float mx = -1e30f;
#pragma unroll 4
        for (int m = 0; m < 24; m++) {
            float a = 0.f;
#pragma unroll
            for (int d = 0; d < 32; d += 4) {
                float4 k4 = *(const float4*)&k_s[w][m * 32 + d];   // broadcast
                a = fmaf(q[d],   k4.x, a); a = fmaf(q[d+1], k4.y, a);
                a = fmaf(q[d+2], k4.z, a); a = fmaf(q[d+3], k4.w, a);
            }
            a = a * scale + bias[m * 24 + lane];                   // coalesced
            p[m] = a;
            mx = fmaxf(mx, a);
        }
        // register softmax (no shfl)
        float sm = 0.f;
#pragma unroll
        for (int m = 0; m < 24; m++) { p[m] = __expf(p[m] - mx); sm += p[m]; }
        float inv = 1.0f / sm;

        // PV: o[d] = sum_m p[m] * v[m][d]  (broadcast reads)
        float o[32];
#pragma unroll
        for (int d = 0; d < 32; d++) o[d] = 0.f;
#pragma unroll 4
        for (int m = 0; m < 24; m++) {
            float pm = p[m];
#pragma unroll
            for (int d = 0; d < 32; d += 4) {
                float4 v4 = *(const float4*)&v_s[w][m * 32 + d];
                o[d]   = fmaf(pm, v4.x, o[d]);
                o[d+1] = fmaf(pm, v4.y, o[d+1]);
                o[d+2] = fmaf(pm, v4.z, o[d+2]);
                o[d+3] = fmaf(pm, v4.w, o[d+3]);
            }
        }
        // coalesced write: [win][head][n][d] contiguous per lane
        bf16* ob = g_attn + (size_t)pair * 768 + lane * 32;
#pragma unroll
        for (int d = 0; d < 32; d += 8) {
            uint4 u;
            u.x = f2bf2u(o[d]*inv,   o[d+1]*inv);
            u.y = f2bf2u(o[d+2]*inv, o[d+3]*inv);
            u.z = f2bf2u(o[d+4]*inv, o[d+5]*inv);
            u.w = f2bf2u(o[d+6]*inv, o[d+7]*inv);
            *(uint4*)(ob + d) = u;
        }
    }
}

// ======================= generic bf16 GEMM (BN=96) ==========================
// EPI: 0 bias->bf16 scatter to qkv layout, 1 bias+gelu->bf16,
//      3 bias+res+scatter->fp32 output
#define GEMM_SMEM (3 * (128 + 96) * 40 * 2)
template <int EPI>
__global__ __launch_bounds__(256) void tc_gemm(
    const bf16* __restrict__ A, const bf16* __restrict__ Bt,
    const float* __restrict__ bias, const float* __restrict__ res,
    void* __restrict__ Cc, int N, int K)
{
    constexpr int LDA = 40;
    constexpr int ASZ = 128 * LDA, BSZ = 96 * LDA;
    extern __shared__ bf16 smem[];
    bf16* Asb = smem;
    bf16* Bsb = smem + 3 * ASZ;

    const int tid  = threadIdx.x;
    const int lane = tid & 31;
    const int wid  = tid >> 5;
    const int wm   = wid & 3;
    const int wn   = wid >> 2;
    const int col0 = blockIdx.x * 96;
    const int row0 = blockIdx.y * 128;
    const int gq = lane >> 2, tg = lane & 3;

    const uint32_t sAb = smem_u32(Asb), sBb = smem_u32(Bsb);

    float acc[2][6][4];
#pragma unroll
    for (int mi = 0; mi < 2; mi++)
#pragma unroll
        for (int ni = 0; ni < 6; ni++)
#pragma unroll
            for (int j = 0; j < 4; j++) acc[mi][ni][j] = 0.f;

    const int nstages = K / 32;

    auto prefetch = [&](int s, int b) {
        const bf16* Ag = A + (size_t)row0 * K + s * 32;
        const bf16* Bg = Bt + (size_t)col0 * K + s * 32;
        uint32_t sA = sAb + (uint32_t)b * ASZ * 2;
        uint32_t sB = sBb + (uint32_t)b * BSZ * 2;
#pragma unroll
        for (int j = 0; j < 2; j++) {
            int idx = tid + j * 256;
            int r = idx >> 2, c = idx & 3;
            cp16(sA + (uint32_t)(r * 80 + c * 16), Ag + (size_t)r * K + c * 8);
        }
        {
            int r = tid >> 2, c = tid & 3;
            cp16(sB + (uint32_t)(r * 80 + c * 16), Bg + (size_t)r * K + c * 8);
        }
        if (tid < 128) {
            int idx = tid + 256;
            int r = idx >> 2, c = idx & 3;
            cp16(sB + (uint32_t)(r * 80 + c * 16), Bg + (size_t)r * K + c * 8);
        }
        CP_COMMIT();
    };

    prefetch(0, 0);
    prefetch(1, 1);

    for (int s = 0; s < nstages; s++) {
        if (s < nstages - 1) CP_WAIT(1); else CP_WAIT(0);
        __syncthreads();
        if (s + 2 < nstages) prefetch(s + 2, (s + 2) % 3);

        const int b = s % 3;
        const uint32_t sA = sAb + (uint32_t)b * ASZ * 2;
        const uint32_t sB = sBb + (uint32_t)b * BSZ * 2;
#pragma unroll
        for (int kk = 0; kk < 32; kk += 16) {
            uint32_t afr[2][4];
            const int arow = wm * 32 + (lane & 15);
            const int acol = kk + (lane >> 4) * 8;
#pragma unroll
            for (int mi = 0; mi < 2; mi++)
                ldsm_x4(afr[mi], sA + (uint32_t)(((arow + mi * 16) * LDA + acol) * 2));

            uint32_t bfr[6][2];
#pragma unroll
            for (int p = 0; p < 3; p++) {
                const int brow = wn * 48 + p * 16 + (lane & 7) + ((lane >> 4) << 3);
                const int bcol = kk + ((lane >> 3) & 1) * 8;
                uint32_t r4[4];
                ldsm_x4(r4, sB + (uint32_t)((brow * LDA + bcol) * 2));
                bfr[2*p][0] = r4[0]; bfr[2*p][1] = r4[1];
                bfr[2*p+1][0] = r4[2]; bfr[2*p+1][1] = r4[3];
            }
#pragma unroll
            for (int mi = 0; mi < 2; mi++)
#pragma unroll
                for (int ni = 0; ni < 6; ni++)
                    mma_bf16(acc[mi][ni], afr[mi], bfr[ni], acc[mi][ni]);
        }
    }

#pragma unroll
    for (int mi = 0; mi < 2; mi++) {
#pragma unroll
        for (int ni = 0; ni < 6; ni++) {
            int row = row0 + wm * 32 + mi * 16 + gq;
            int col = col0 + wn * 48 + ni * 8 + tg * 2;
            float b0 = bias[col], b1 = bias[col + 1];
#pragma unroll
            for (int hh = 0; hh < 2; hh++) {
                int r = row + hh * 8;
                float v0 = acc[mi][ni][hh * 2]     + b0;
                float v1 = acc[mi][ni][hh * 2 + 1] + b1;
                if (EPI == 1) {
                    v0 = 0.5f * v0 * (1.0f + erff(v0 * 0.70710678118654752f));
                    v1 = 0.5f * v1 * (1.0f + erff(v1 * 0.70710678118654752f));
                }
                if (EPI == 0) {
                    // scatter into [win][head][q|k|v][24][32] layout
                    int wi2 = r / 24, n2 = r - wi2 * 24;
                    int which = col / 192;
                    int rem = col - which * 192;
                    int h2 = rem >> 5, d2 = rem & 31;
                    bf16* cp_ = (bf16*)Cc +
                        ((((size_t)wi2 * 6 + h2) * 3 + which) * 768 + n2 * 32 + d2);
                    *(__nv_bfloat162*)cp_ = __floats2bfloat162_rn(v0, v1);
                } else if (EPI == 3) {
                    const float* rp = res + (size_t)r * 192 + col;
                    v0 += rp[0]; v1 += rp[1];
                    size_t off = token_src_offset(r) + col;
                    *(float2*)((float*)Cc + off) = make_float2(v0, v1);
                } else {
                    bf16* cp_ = (bf16*)Cc + (size_t)r * N + col;
                    *(__nv_bfloat162*)cp_ = __floats2bfloat162_rn(v0, v1);
                }
            }
        }
    }
}

// ================= proj GEMM (BN=192) + residual(from x) + LN2 ==============
// A operand read from attention-native layout [win][head][24][32];
// K-stage s == head index, so remap is cheap.
#define PROJ_SMEM (3 * (128 + 192) * 40 * 2)
__global__ __launch_bounds__(256) void proj_ln2_kernel(
    const bf16* __restrict__ A, const bf16* __restrict__ Bt,
    const float* __restrict__ bias, const float* __restrict__ x,
    const float* __restrict__ gam, const float* __restrict__ bet)
{
    constexpr int LDA = 40, K = 192;
    constexpr int ASZ = 128 * LDA, BSZ = 192 * LDA;
    extern __shared__ bf16 smem[];
    bf16* Asb = smem;
    bf16* Bsb = smem + 3 * ASZ;
    __shared__ float s_sum[128][2];
    __shared__ float s_sq [128][2];

    const int tid  = threadIdx.x;
    const int lane = tid & 31;
    const int wid  = tid >> 5;
    const int wm   = wid & 3;
    const int wn   = wid >> 2;
    const int row0 = blockIdx.x * 128;
    const int gq = lane >> 2, tg = lane & 3;

    const uint32_t sAb = smem_u32(Asb), sBb = smem_u32(Bsb);

    float acc[2][12][4];
#pragma unroll
    for (int mi = 0; mi < 2; mi++)
#pragma unroll
        for (int ni = 0; ni < 12; ni++)
#pragma unroll
            for (int j = 0; j < 4; j++) acc[mi][ni][j] = 0.f;

    const int nstages = 6;

    auto prefetch = [&](int s, int b) {
        const bf16* Bg = Bt + (size_t)s * 32;
        uint32_t sA = sAb + (uint32_t)b * ASZ * 2;
        uint32_t sB = sBb + (uint32_t)b * BSZ * 2;
#pragma unroll
        for (int j = 0; j < 2; j++) {
            int idx = tid + j * 256;
            int r = idx >> 2, c4 = idx & 3;
            int rg = row0 + r;
            int win = rg / 24, n2 = rg - win * 24;
            // A[rg][s*32 + c4*8] in [win][head=s][n][d] layout
            const bf16* src = A + ((size_t)win * 6 + s) * 768 + n2 * 32 + c4 * 8;
            cp16(sA + (uint32_t)(r * 80 + c4 * 16), src);
        }
#pragma unroll
        for (int j = 0; j < 3; j++) {
            int idx = tid + j * 256;
            int r = idx >> 2, c = idx & 3;
            cp16(sB + (uint32_t)(r * 80 + c * 16), Bg + (size_t)r * K + c * 8);
        }
        CP_COMMIT();
    };

    prefetch(0, 0);
    prefetch(1, 1);

    for (int s = 0; s < nstages; s++) {
        if (s < nstages - 1) CP_WAIT(1); else CP_WAIT(0);
        __syncthreads();
        if (s + 2 < nstages) prefetch(s + 2, (s + 2) % 3);

        const int b = s % 3;
        const uint32_t sA = sAb + (uint32_t)b * ASZ * 2;
        const uint32_t sB = sBb + (uint32_t)b * BSZ * 2;
#pragma unroll
        for (int kk = 0; kk < 32; kk += 16) {
            uint32_t afr[2][4];
            const int arow = wm * 32 + (lane & 15);
            const int acol = kk + (lane >> 4) * 8;
#pragma unroll
            for (int mi = 0; mi < 2; mi++)
                ldsm_x4(afr[mi], sA + (uint32_t)(((arow + mi * 16) * LDA + acol) * 2));

            uint32_t bfr[12][2];
#pragma unroll
            for (int p = 0; p < 6; p++) {
                const int brow = wn * 96 + p * 16 + (lane & 7) + ((lane >> 4) << 3);
                const int bcol = kk + ((lane >> 3) & 1) * 8;
                uint32_t r4[4];
                ldsm_x4(r4, sB + (uint32_t)((brow * LDA + bcol) * 2));
                bfr[2*p][0] = r4[0]; bfr[2*p][1] = r4[1];
                bfr[2*p+1][0] = r4[2]; bfr[2*p+1][1] = r4[3];
            }
#pragma unroll
            for (int mi = 0; mi < 2; mi++)
#pragma unroll
                for (int ni = 0; ni < 12; ni++)
                    mma_bf16(acc[mi][ni], afr[mi], bfr[ni], acc[mi][ni]);
        }
    }

#pragma unroll
    for (int mi = 0; mi < 2; mi++) {
#pragma unroll
        for (int hh = 0; hh < 2; hh++) {
            int rl = wm * 32 + mi * 16 + gq + hh * 8;
            int r  = row0 + rl;
            size_t roff = token_src_offset(r);
            float s1 = 0.f, s2 = 0.f;
#pragma unroll
            for (int ni = 0; ni < 12; ni++) {
                int col = wn * 96 + ni * 8 + tg * 2;
                float2 rx = *(const float2*)(x + roff + col);
                float v0 = acc[mi][ni][hh*2]     + bias[col]     + rx.x;
                float v1 = acc[mi][ni][hh*2 + 1] + bias[col + 1] + rx.y;
                acc[mi][ni][hh*2]     = v0;
                acc[mi][ni][hh*2 + 1] = v1;
                s1 += v0 + v1;
                s2 += v0 * v0 + v1 * v1;
            }
            s1 += __shfl_xor_sync(0xffffffffu, s1, 1);
            s1 += __shfl_xor_sync(0xffffffffu, s1, 2);
            s2 += __shfl_xor_sync(0xffffffffu, s2, 1);
            s2 += __shfl_xor_sync(0xffffffffu, s2, 2);
            if (tg == 0) { s_sum[rl][wn] = s1; s_sq[rl][wn] = s2; }
        }
    }
    __syncthreads();
#pragma unroll
    for (int mi = 0; mi < 2; mi++) {
#pragma unroll
        for (int hh = 0; hh < 2; hh++) {
            int rl = wm * 32 + mi * 16 + gq + hh * 8;
            int r  = row0 + rl;
            float S1 = s_sum[rl][0] + s_sum[rl][1];
            float S2 = s_sq [rl][0] + s_sq [rl][1];
            float mean = S1 * (1.0f / 192.0f);
            float var  = S2 * (1.0f / 192.0f) - mean * mean;
            float rstd = rsqrtf(var + 1e-5f);
#pragma unroll
            for (int ni = 0; ni < 12; ni++) {
                int col = wn * 96 + ni * 8 + tg * 2;
                float v0 = acc[mi][ni][hh*2], v1 = acc[mi][ni][hh*2 + 1];
                *(float2*)(g_x2 + (size_t)r * 192 + col) = make_float2(v0, v1);
                float n0 = (v0 - mean) * rstd * gam[col]     + bet[col];
                float n1 = (v1 - mean) * rstd * gam[col + 1] + bet[col + 1];
                *(__nv_bfloat162*)(g_h + (size_t)r * 192 + col) =
                    __floats2bfloat162_rn(n0, n1);
            }
        }
    }
}

// ---------------- host launcher ----------------
extern "C" void kernel_launch(void* const* d_in, const int* in_sizes, int n_in,
                              void* d_out, int out_size)
{
    const float* x      = (const float*)d_in[0];
    const float* ln1_g  = (const float*)d_in[1];
    const float* ln1_b  = (const float*)d_in[2];
    const float* qkv_w  = (const float*)d_in[3];
    const float* qkv_b  = (const float*)d_in[4];
    const float* btab   = (const float*)d_in[5];
    const float* proj_w = (const float*)d_in[6];
    const float* proj_b = (const float*)d_in[7];
    const float* ln2_g  = (const float*)d_in[8];
    const float* ln2_b  = (const float*)d_in[9];
    const float* mlp_w1 = (const float*)d_in[10];
    const float* mlp_b1 = (const float*)d_in[11];
    const float* mlp_w2 = (const float*)d_in[12];
    const float* mlp_b2 = (const float*)d_in[13];
    const int*   rel_idx= (const int*)d_in[14];
    float*       out    = (float*)d_out;

    bf16 *p_h, *p_qkv, *p_attn, *p_hid;
    float *p_x2;
    bf16 *p_qkv_wt, *p_proj_wt, *p_w1t, *p_w2t;
    cudaGetSymbolAddress((void**)&p_h,    g_h);
    cudaGetSymbolAddress((void**)&p_qkv,  g_qkv);
    cudaGetSymbolAddress((void**)&p_attn, g_attn);
    cudaGetSymbolAddress((void**)&p_x2,   g_x2);
    cudaGetSymbolAddress((void**)&p_hid,  g_hid);
    cudaGetSymbolAddress((void**)&p_qkv_wt,  g_qkv_wt);
    cudaGetSymbolAddress((void**)&p_proj_wt, g_proj_wt);
    cudaGetSymbolAddress((void**)&p_w1t,  g_w1t);
    cudaGetSymbolAddress((void**)&p_w2t,  g_w2t);

    cudaFuncSetAttribute(tc_gemm<0>, cudaFuncAttributeMaxDynamicSharedMemorySize, GEMM_SMEM);
    cudaFuncSetAttribute(tc_gemm<1>, cudaFuncAttributeMaxDynamicSharedMemorySize, GEMM_SMEM);
    cudaFuncSetAttribute(tc_gemm<3>, cudaFuncAttributeMaxDynamicSharedMemorySize, GEMM_SMEM);
    cudaFuncSetAttribute(proj_ln2_kernel, cudaFuncAttributeMaxDynamicSharedMemorySize, PROJ_SMEM);

    transpose_all_kernel<<<432, dim3(32, 8)>>>(qkv_w, proj_w, mlp_w1, mlp_w2,
                                               p_qkv_wt, p_proj_wt, p_w1t, p_w2t);
    bias_precompute_kernel<<<HEADS, 576>>>(btab, rel_idx);

    gather_ln1_kernel<<<NTOK_TOTAL / 8, 256>>>(x, ln1_g, ln1_b);

    const int Mb = NTOK_TOTAL / 128;  // 1008
    tc_gemm<0><<<dim3(6, Mb), 256, GEMM_SMEM>>>(p_h, p_qkv_wt, qkv_b, nullptr, p_qkv, 576, 192);
    attn_kernel<<<NWIN * HEADS / 8, 256>>>();
    proj_ln2_kernel<<<Mb, 256, PROJ_SMEM>>>(p_attn, p_proj_wt, proj_b, x, ln2_g, ln2_b);
    tc_gemm<1><<<dim3(8, Mb), 256, GEMM_SMEM>>>(p_h, p_w1t, mlp_b1, nullptr, p_hid, 768, 192);
    tc_gemm<3><<<dim3(2, Mb), 256, GEMM_SMEM>>>(p_hid, p_w2t, mlp_b2, p_x2, out, 192, 768);
}

// round 10
// speedup vs baseline: 3.8478x; 1.0166x over previous
#include <cuda_runtime.h>
#include <cuda_bf16.h>
#include <math.h>
#include <stdint.h>

typedef __nv_bfloat16 bf16;

// ---------------- problem constants ----------------
#define NTOK_TOTAL 129024   // 5376 windows * 24 tokens
#define NWIN       5376
#define HEADS      6

// ---------------- scratch (device globals) ----------------
__device__ float g_x2  [(size_t)NTOK_TOTAL * 192];   // trunk after proj (fp32)
__device__ bf16  g_h   [(size_t)NTOK_TOTAL * 192];   // LN out (bf16, GEMM A)
// qkv in attention-native layout: [win][head][q|k|v][24][32]
__device__ bf16  g_qkv [(size_t)NTOK_TOTAL * 576];
// attn out in [win][head][24][32] layout
__device__ bf16  g_attn[(size_t)NTOK_TOTAL * 192];
__device__ bf16  g_hid [(size_t)NTOK_TOTAL * 768];
__device__ float g_bias6[HEADS * 576];               // bias[h][m][n] (transposed!)
// pre-transposed bf16 weights (K-major: Wt[N][K])
__device__ bf16 g_qkv_wt [576 * 192];
__device__ bf16 g_proj_wt[192 * 192];
__device__ bf16 g_w1t    [768 * 192];
__device__ bf16 g_w2t    [192 * 768];

// ---------------- helpers ----------------
__device__ __forceinline__ size_t token_src_offset(int t) {
    int wi = t / 24, n = t % 24;
    int i3 = n / 12, j3 = (n >> 1) % 6, k3 = n & 1;
    int d0 = wi % 7;  int r = wi / 7;
    int w0 = r % 16;  r /= 16;
    int h0 = r % 24;  int b0 = r / 24;
    return ((((size_t)b0 * 48 + (h0 * 2 + i3)) * 96 + (w0 * 6 + j3)) * 14
            + (d0 * 2 + k3)) * 192;
}
__device__ __forceinline__ float warp_sum(float v) {
#pragma unroll
    for (int o = 16; o; o >>= 1) v += __shfl_xor_sync(0xffffffffu, v, o);
    return v;
}
__device__ __forceinline__ uint32_t smem_u32(const void* p) {
    uint32_t a;
    asm("{ .reg .u64 t; cvta.to.shared.u64 t, %1; cvt.u32.u64 %0, t; }" : "=r"(a) : "l"(p));
    return a;
}
__device__ __forceinline__ void cp16(uint32_t dst, const void* src) {
    asm volatile("cp.async.cg.shared.global [%0], [%1], 16;" :: "r"(dst), "l"(src));
}
#define CP_COMMIT() asm volatile("cp.async.commit_group;" ::: "memory")
#define CP_WAIT(n)  asm volatile("cp.async.wait_group %0;" :: "n"(n) : "memory")

__device__ __forceinline__ void ldsm_x4(uint32_t* r, uint32_t a) {
    asm volatile("ldmatrix.sync.aligned.m8n8.x4.shared.b16 {%0,%1,%2,%3}, [%4];"
                 : "=r"(r[0]), "=r"(r[1]), "=r"(r[2]), "=r"(r[3]) : "r"(a));
}
__device__ __forceinline__ void mma_bf16(float* d, const uint32_t* a,
                                         const uint32_t* b, const float* c) {
    asm volatile(
        "mma.sync.aligned.m16n8k16.row.col.f32.bf16.bf16.f32 "
        "{%0,%1,%2,%3}, {%4,%5,%6,%7}, {%8,%9}, {%10,%11,%12,%13};"
        : "=f"(d[0]), "=f"(d[1]), "=f"(d[2]), "=f"(d[3])
        : "r"(a[0]), "r"(a[1]), "r"(a[2]), "r"(a[3]),
          "r"(b[0]), "r"(b[1]),
          "f"(c[0]), "f"(c[1]), "f"(c[2]), "f"(c[3]));
}
__device__ __forceinline__ float2 bf2f2(uint32_t u) {
    __nv_bfloat162 b = *reinterpret_cast<__nv_bfloat162*>(&u);
    return __bfloat1622float2(b);
}
__device__ __forceinline__ uint32_t f2bf2u(float lo, float hi) {
    __nv_bfloat162 b = __floats2bfloat162_rn(lo, hi);
    return *reinterpret_cast<uint32_t*>(&b);
}

// ---------------- one-shot weight transpose (all 4 weights) ----------------
__global__ void transpose_all_kernel(
    const float* __restrict__ qkv_w, const float* __restrict__ proj_w,
    const float* __restrict__ w1, const float* __restrict__ w2,
    bf16* __restrict__ qkv_wt, bf16* __restrict__ proj_wt,
    bf16* __restrict__ w1t, bf16* __restrict__ w2t)
{
    __shared__ float t[32][33];
    int bid = blockIdx.x;
    const float* W; bf16* Wt; int K, N, loc;
    if (bid < 108)      { W = qkv_w;  Wt = qkv_wt;  K = 192; N = 576; loc = bid; }
    else if (bid < 144) { W = proj_w; Wt = proj_wt; K = 192; N = 192; loc = bid - 108; }
    else if (bid < 288) { W = w1;     Wt = w1t;     K = 192; N = 768; loc = bid - 144; }
    else                { W = w2;     Wt = w2t;     K = 768; N = 192; loc = bid - 288; }
    int Kt = K / 32;
    int kb = (loc % Kt) * 32, nb = (loc / Kt) * 32;
    int x = threadIdx.x, y = threadIdx.y;
#pragma unroll
    for (int j = 0; j < 32; j += 8) t[y + j][x] = W[(size_t)(kb + y + j) * N + nb + x];
    __syncthreads();
#pragma unroll
    for (int j = 0; j < 32; j += 8)
        Wt[(size_t)(nb + y + j) * K + kb + x] = __float2bfloat16(t[x][y + j]);
}

// ---------------- bias precompute (TRANSPOSED): bias6[h*576 + m*24 + n] -----
__global__ void bias_precompute_kernel(const float* __restrict__ bias_table,
                                       const int* __restrict__ rel_index)
{
    int h = blockIdx.x, idx = threadIdx.x;   // idx = m*24 + n
    if (idx < 576) {
        int m = idx / 24, n = idx - m * 24;
        g_bias6[h * 576 + idx] = bias_table[rel_index[n * 24 + m] * HEADS + h];
    }
}

// ---------------- gather + LN1 ----------------
__global__ __launch_bounds__(256) void gather_ln1_kernel(
    const float* __restrict__ x, const float* __restrict__ gam, const float* __restrict__ bet)
{
    int t = blockIdx.x * 8 + (threadIdx.x >> 5);
    int lane = threadIdx.x & 31;
    size_t src = token_src_offset(t);
    float v[6]; float s = 0.f;
#pragma unroll
    for (int q = 0; q < 6; q++) { v[q] = x[src + lane + q * 32]; s += v[q]; }
    float mean = warp_sum(s) * (1.0f / 192.0f);
    float vs = 0.f;
#pragma unroll
    for (int q = 0; q < 6; q++) { float d = v[q] - mean; vs += d * d; }
    float rstd = rsqrtf(warp_sum(vs) * (1.0f / 192.0f) + 1e-5f);
    size_t dst = (size_t)t * 192;
#pragma unroll
    for (int q = 0; q < 6; q++) {
        int c = lane + q * 32;
        g_h[dst + c] = __float2bfloat16((v[q] - mean) * rstd * gam[c] + bet[c]);
    }
}

// ---------------- attention: lane = query row, shfl-free softmax ------------
__global__ __launch_bounds__(256) void attn_kernel()
{
    __shared__ float k_s[8][768];   // [m*32 + d]
    __shared__ float v_s[8][768];
    const int w = threadIdx.x >> 5, lane = threadIdx.x & 31;
    const int pair = blockIdx.x * 8 + w;
    const int h = pair % 6;
    const bf16* base = g_qkv + (size_t)pair * 2304;   // [q 768 | k 768 | v 768]
    const float* bias = g_bias6 + h * 576;            // [m][n]

    // cooperative coalesced k, v loads -> fp32 smem
#pragma unroll
    for (int j = 0; j < 3; j++) {
        int idx = (lane + j * 32) * 8;
        uint4 uk = *(const uint4*)(base + 768 + idx);
        uint4 uv = *(const uint4*)(base + 1536 + idx);
        float2 f;
        f = bf2f2(uk.x); k_s[w][idx+0] = f.x; k_s[w][idx+1] = f.y;
        f = bf2f2(uk.y); k_s[w][idx+2] = f.x; k_s[w][idx+3] = f.y;
        f = bf2f2(uk.z); k_s[w][idx+4] = f.x; k_s[w][idx+5] = f.y;
        f = bf2f2(uk.w); k_s[w][idx+6] = f.x; k_s[w][idx+7] = f.y;
        f = bf2f2(uv.x); v_s[w][idx+0] = f.x; v_s[w][idx+1] = f.y;
        f = bf2f2(uv.y); v_s[w][idx+2] = f.x; v_s[w][idx+3] = f.y;
        f = bf2f2(uv.z); v_s[w][idx+4] = f.x; v_s[w][idx+5] = f.y;
        f = bf2f2(uv.w); v_s[w][idx+6] = f.x; v_s[w][idx+7] = f.y;
    }
    __syncwarp();

    if (lane < 24) {
        float q[32];
        const bf16* qp = base + lane * 32;
#pragma unroll
        for (int d = 0; d < 32; d += 8) {
            uint4 u = *(const uint4*)(qp + d);
            float2 f;
            f = bf2f2(u.x); q[d+0] = f.x; q[d+1] = f.y;
            f = bf2f2(u.y); q[d+2] = f.x; q[d+3] = f.y;
            f = bf2f2(u.z); q[d+4] = f.x; q[d+5] = f.y;
            f = bf2f2(u.w); q[d+6] = f.x; q[d+7] = f.y;
        }

        const float scale = 0.17677669529663687f;  // 32^-0.5
        float p[24];
        float mx = -1e30f;
#pragma unroll 4
        for (int m = 0; m < 24; m++) {
            float a = 0.f;
#pragma unroll
            for (int d = 0; d < 32; d += 4) {
                float4 k4 = *(const float4*)&k_s[w][m * 32 + d];   // broadcast
                a = fmaf(q[d],   k4.x, a); a = fmaf(q[d+1], k4.y, a);
                a = fmaf(q[d+2], k4.z, a); a = fmaf(q[d+3], k4.w, a);
            }
            a = a * scale + bias[m * 24 + lane];                   // coalesced
            p[m] = a;
            mx = fmaxf(mx, a);
        }
        float sm = 0.f;
#pragma unroll
        for (int m = 0; m < 24; m++) { p[m] = __expf(p[m] - mx); sm += p[m]; }
        float inv = 1.0f / sm;

        float o[32];
#pragma unroll
        for (int d = 0; d < 32; d++) o[d] = 0.f;
#pragma unroll 4
        for (int m = 0; m < 24; m++) {
            float pm = p[m];
#pragma unroll
            for (int d = 0; d < 32; d += 4) {
                float4 v4 = *(const float4*)&v_s[w][m * 32 + d];
                o[d]   = fmaf(pm, v4.x, o[d]);
                o[d+1] = fmaf(pm, v4.y, o[d+1]);
                o[d+2] = fmaf(pm, v4.z, o[d+2]);
                o[d+3] = fmaf(pm, v4.w, o[d+3]);
            }
        }
        bf16* ob = g_attn + (size_t)pair * 768 + lane * 32;
#pragma unroll
        for (int d = 0; d < 32; d += 8) {
            uint4 u;
            u.x = f2bf2u(o[d]*inv,   o[d+1]*inv);
            u.y = f2bf2u(o[d+2]*inv, o[d+3]*inv);
            u.z = f2bf2u(o[d+4]*inv, o[d+5]*inv);
            u.w = f2bf2u(o[d+6]*inv, o[d+7]*inv);
            *(uint4*)(ob + d) = u;
        }
    }
}

// ======================= generic bf16 GEMM (BN=96) ==========================
// EPI: 0 bias->bf16 scatter to qkv layout, 1 bias+gelu->bf16,
//      3 bias+res+scatter->fp32 output
#define GEMM_SMEM (3 * (128 + 96) * 40 * 2)
template <int EPI>
__global__ __launch_bounds__(256, 3) void tc_gemm(
    const bf16* __restrict__ A, const bf16* __restrict__ Bt,
    const float* __restrict__ bias, const float* __restrict__ res,
    void* __restrict__ Cc, int N, int K)
{
    constexpr int LDA = 40;
    constexpr int ASZ = 128 * LDA, BSZ = 96 * LDA;
    extern __shared__ bf16 smem[];
    bf16* Asb = smem;
    bf16* Bsb = smem + 3 * ASZ;

    const int tid  = threadIdx.x;
    const int lane = tid & 31;
    const int wid  = tid >> 5;
    const int wm   = wid & 3;
    const int wn   = wid >> 2;
    const int col0 = blockIdx.x * 96;
    const int row0 = blockIdx.y * 128;
    const int gq = lane >> 2, tg = lane & 3;

    const uint32_t sAb = smem_u32(Asb), sBb = smem_u32(Bsb);

    float acc[2][6][4];
#pragma unroll
    for (int mi = 0; mi < 2; mi++)
#pragma unroll
        for (int ni = 0; ni < 6; ni++)
#pragma unroll
            for (int j = 0; j < 4; j++) acc[mi][ni][j] = 0.f;

    const int nstages = K / 32;

    auto prefetch = [&](int s, int b) {
        const bf16* Ag = A + (size_t)row0 * K + s * 32;
        const bf16* Bg = Bt + (size_t)col0 * K + s * 32;
        uint32_t sA = sAb + (uint32_t)b * ASZ * 2;
        uint32_t sB = sBb + (uint32_t)b * BSZ * 2;
#pragma unroll
        for (int j = 0; j < 2; j++) {
            int idx = tid + j * 256;
            int r = idx >> 2, c = idx & 3;
            cp16(sA + (uint32_t)(r * 80 + c * 16), Ag + (size_t)r * K + c * 8);
        }
        {
            int r = tid >> 2, c = tid & 3;
            cp16(sB + (uint32_t)(r * 80 + c * 16), Bg + (size_t)r * K + c * 8);
        }
        if (tid < 128) {
            int idx = tid + 256;
            int r = idx >> 2, c = idx & 3;
            cp16(sB + (uint32_t)(r * 80 + c * 16), Bg + (size_t)r * K + c * 8);
        }
        CP_COMMIT();
    };

    prefetch(0, 0);
    prefetch(1, 1);

    for (int s = 0; s < nstages; s++) {
        if (s < nstages - 1) CP_WAIT(1); else CP_WAIT(0);
        __syncthreads();
        if (s + 2 < nstages) prefetch(s + 2, (s + 2) % 3);

        const int b = s % 3;
        const uint32_t sA = sAb + (uint32_t)b * ASZ * 2;
        const uint32_t sB = sBb + (uint32_t)b * BSZ * 2;
#pragma unroll
        for (int kk = 0; kk < 32; kk += 16) {
            uint32_t afr[2][4];
            const int arow = wm * 32 + (lane & 15);
            const int acol = kk + (lane >> 4) * 8;
#pragma unroll
            for (int mi = 0; mi < 2; mi++)
                ldsm_x4(afr[mi], sA + (uint32_t)(((arow + mi * 16) * LDA + acol) * 2));

            uint32_t bfr[6][2];
#pragma unroll
            for (int p = 0; p < 3; p++) {
                const int brow = wn * 48 + p * 16 + (lane & 7) + ((lane >> 4) << 3);
                const int bcol = kk + ((lane >> 3) & 1) * 8;
                uint32_t r4[4];
                ldsm_x4(r4, sB + (uint32_t)((brow * LDA + bcol) * 2));
                bfr[2*p][0] = r4[0]; bfr[2*p][1] = r4[1];
                bfr[2*p+1][0] = r4[2]; bfr[2*p+1][1] = r4[3];
            }
#pragma unroll
            for (int mi = 0; mi < 2; mi++)
#pragma unroll
                for (int ni = 0; ni < 6; ni++)
                    mma_bf16(acc[mi][ni], afr[mi], bfr[ni], acc[mi][ni]);
        }
    }

#pragma unroll
    for (int mi = 0; mi < 2; mi++) {
#pragma unroll
        for (int ni = 0; ni < 6; ni++) {
            int row = row0 + wm * 32 + mi * 16 + gq;
            int col = col0 + wn * 48 + ni * 8 + tg * 2;
            float b0 = bias[col], b1 = bias[col + 1];
#pragma unroll
            for (int hh = 0; hh < 2; hh++) {
                int r = row + hh * 8;
                float v0 = acc[mi][ni][hh * 2]     + b0;
                float v1 = acc[mi][ni][hh * 2 + 1] + b1;
                if (EPI == 1) {
                    v0 = 0.5f * v0 * (1.0f + erff(v0 * 0.70710678118654752f));
                    v1 = 0.5f * v1 * (1.0f + erff(v1 * 0.70710678118654752f));
                }
                if (EPI == 0) {
                    int wi2 = r / 24, n2 = r - wi2 * 24;
                    int which = col / 192;
                    int rem = col - which * 192;
                    int h2 = rem >> 5, d2 = rem & 31;
                    bf16* cp_ = (bf16*)Cc +
                        ((((size_t)wi2 * 6 + h2) * 3 + which) * 768 + n2 * 32 + d2);
                    *(__nv_bfloat162*)cp_ = __floats2bfloat162_rn(v0, v1);
                } else if (EPI == 3) {
                    const float* rp = res + (size_t)r * 192 + col;
                    v0 += rp[0]; v1 += rp[1];
                    size_t off = token_src_offset(r) + col;
                    *(float2*)((float*)Cc + off) = make_float2(v0, v1);
                } else {
                    bf16* cp_ = (bf16*)Cc + (size_t)r * N + col;
                    *(__nv_bfloat162*)cp_ = __floats2bfloat162_rn(v0, v1);
                }
            }
        }
    }
}

// ===== proj GEMM (BM=64, BN=192) + residual(from x) + LN2, 3 CTAs/SM ========
// warp grid 2x4: wm in {0,1} (32 rows), wn in {0..3} (48 cols)
#define PROJ_SMEM (3 * (64 + 192) * 40 * 2)
__global__ __launch_bounds__(256, 3) void proj_ln2_kernel(
    const bf16* __restrict__ A, const bf16* __restrict__ Bt,
    const float* __restrict__ bias, const float* __restrict__ x,
    const float* __restrict__ gam, const float* __restrict__ bet)
{
    constexpr int LDA = 40, K = 192;
    constexpr int ASZ = 64 * LDA, BSZ = 192 * LDA;
    extern __shared__ bf16 smem[];
    bf16* Asb = smem;
    bf16* Bsb = smem + 3 * ASZ;
    __shared__ float s_sum[64][4];
    __shared__ float s_sq [64][4];

    const int tid  = threadIdx.x;
    const int lane = tid & 31;
    const int wid  = tid >> 5;
    const int wm   = wid & 1;
    const int wn   = wid >> 1;
    const int row0 = blockIdx.x * 64;
    const int gq = lane >> 2, tg = lane & 3;

    const uint32_t sAb = smem_u32(Asb), sBb = smem_u32(Bsb);

    float acc[2][6][4];
#pragma unroll
    for (int mi = 0; mi < 2; mi++)
#pragma unroll
        for (int ni = 0; ni < 6; ni++)
#pragma unroll
            for (int j = 0; j < 4; j++) acc[mi][ni][j] = 0.f;

    const int nstages = 6;

    auto prefetch = [&](int s, int b) {
        const bf16* Bg = Bt + (size_t)s * 32;
        uint32_t sA = sAb + (uint32_t)b * ASZ * 2;
        uint32_t sB = sBb + (uint32_t)b * BSZ * 2;
        {
            int r = tid >> 2, c4 = tid & 3;      // 64 rows x 4 chunks = 256
            int rg = row0 + r;
            int win = rg / 24, n2 = rg - win * 24;
            const bf16* src = A + ((size_t)win * 6 + s) * 768 + n2 * 32 + c4 * 8;
            cp16(sA + (uint32_t)(r * 80 + c4 * 16), src);
        }
#pragma unroll
        for (int j = 0; j < 3; j++) {            // 192 rows x 4 chunks = 768
            int idx = tid + j * 256;
            int r = idx >> 2, c = idx & 3;
            cp16(sB + (uint32_t)(r * 80 + c * 16), Bg + (size_t)r * K + c * 8);
        }
        CP_COMMIT();
    };

    prefetch(0, 0);
    prefetch(1, 1);

    for (int s = 0; s < nstages; s++) {
        if (s < nstages - 1) CP_WAIT(1); else CP_WAIT(0);
        __syncthreads();
        if (s + 2 < nstages) prefetch(s + 2, (s + 2) % 3);

        const int b = s % 3;
        const uint32_t sA = sAb + (uint32_t)b * ASZ * 2;
        const uint32_t sB = sBb + (uint32_t)b * BSZ * 2;
#pragma unroll
        for (int kk = 0; kk < 32; kk += 16) {
            uint32_t afr[2][4];
            const int arow = wm * 32 + (lane & 15);
            const int acol = kk + (lane >> 4) * 8;
#pragma unroll
            for (int mi = 0; mi < 2; mi++)
                ldsm_x4(afr[mi], sA + (uint32_t)(((arow + mi * 16) * LDA + acol) * 2));

            uint32_t bfr[6][2];
#pragma unroll
            for (int p = 0; p < 3; p++) {
                const int brow = wn * 48 + p * 16 + (lane & 7) + ((lane >> 4) << 3);
                const int bcol = kk + ((lane >> 3) & 1) * 8;
                uint32_t r4[4];
                ldsm_x4(r4, sB + (uint32_t)((brow * LDA + bcol) * 2));
                bfr[2*p][0] = r4[0]; bfr[2*p][1] = r4[1];
                bfr[2*p+1][0] = r4[2]; bfr[2*p+1][1] = r4[3];
            }
#pragma unroll
            for (int mi = 0; mi < 2; mi++)
#pragma unroll
                for (int ni = 0; ni < 6; ni++)
                    mma_bf16(acc[mi][ni], afr[mi], bfr[ni], acc[mi][ni]);
        }
    }

    // ---- epilogue: bias + residual(from x) + row stats ----
#pragma unroll
    for (int mi = 0; mi < 2; mi++) {
#pragma unroll
        for (int hh = 0; hh < 2; hh++) {
            int rl = wm * 32 + mi * 16 + gq + hh * 8;
            int r  = row0 + rl;
            size_t roff = token_src_offset(r);
            float s1 = 0.f, s2 = 0.f;
#pragma unroll
            for (int ni = 0; ni < 6; ni++) {
                int col = wn * 48 + ni * 8 + tg * 2;
                float2 rx = *(const float2*)(x + roff + col);
                float v0 = acc[mi][ni][hh*2]     + bias[col]     + rx.x;
                float v1 = acc[mi][ni][hh*2 + 1] + bias[col + 1] + rx.y;
                acc[mi][ni][hh*2]     = v0;
                acc[mi][ni][hh*2 + 1] = v1;
                s1 += v0 + v1;
                s2 += v0 * v0 + v1 * v1;
            }
            s1 += __shfl_xor_sync(0xffffffffu, s1, 1);
            s1 += __shfl_xor_sync(0xffffffffu, s1, 2);
            s2 += __shfl_xor_sync(0xffffffffu, s2, 1);
            s2 += __shfl_xor_sync(0xffffffffu, s2, 2);
            if (tg == 0) { s_sum[rl][wn] = s1; s_sq[rl][wn] = s2; }
        }
    }
    __syncthreads();
#pragma unroll
    for (int mi = 0; mi < 2; mi++) {
#pragma unroll
        for (int hh = 0; hh < 2; hh++) {
            int rl = wm * 32 + mi * 16 + gq + hh * 8;
            int r  = row0 + rl;
            float S1 = s_sum[rl][0] + s_sum[rl][1] + s_sum[rl][2] + s_sum[rl][3];
            float S2 = s_sq [rl][0] + s_sq [rl][1] + s_sq [rl][2] + s_sq [rl][3];
            float mean = S1 * (1.0f / 192.0f);
            float var  = S2 * (1.0f / 192.0f) - mean * mean;
            float rstd = rsqrtf(var + 1e-5f);
#pragma unroll
            for (int ni = 0; ni < 6; ni++) {
                int col = wn * 48 + ni * 8 + tg * 2;
                float v0 = acc[mi][ni][hh*2], v1 = acc[mi][ni][hh*2 + 1];
                *(float2*)(g_x2 + (size_t)r * 192 + col) = make_float2(v0, v1);
                float n0 = (v0 - mean) * rstd * gam[col]     + bet[col];
                float n1 = (v1 - mean) * rstd * gam[col + 1] + bet[col + 1];
                *(__nv_bfloat162*)(g_h + (size_t)r * 192 + col) =
                    __floats2bfloat162_rn(n0, n1);
            }
        }
    }
}

// ---------------- host launcher ----------------
extern "C" void kernel_launch(void* const* d_in, const int* in_sizes, int n_in,
                              void* d_out, int out_size)
{
    const float* x      = (const float*)d_in[0];
    const float* ln1_g  = (const float*)d_in[1];
    const float* ln1_b  = (const float*)d_in[2];
    const float* qkv_w  = (const float*)d_in[3];
    const float* qkv_b  = (const float*)d_in[4];
    const float* btab   = (const float*)d_in[5];
    const float* proj_w = (const float*)d_in[6];
    const float* proj_b = (const float*)d_in[7];
    const float* ln2_g  = (const float*)d_in[8];
    const float* ln2_b  = (const float*)d_in[9];
    const float* mlp_w1 = (const float*)d_in[10];
    const float* mlp_b1 = (const float*)d_in[11];
    const float* mlp_w2 = (const float*)d_in[12];
    const float* mlp_b2 = (const float*)d_in[13];
    const int*   rel_idx= (const int*)d_in[14];
    float*       out    = (float*)d_out;

    bf16 *p_h, *p_qkv, *p_attn, *p_hid;
    float *p_x2;
    bf16 *p_qkv_wt, *p_proj_wt, *p_w1t, *p_w2t;
    cudaGetSymbolAddress((void**)&p_h,    g_h);
    cudaGetSymbolAddress((void**)&p_qkv,  g_qkv);
    cudaGetSymbolAddress((void**)&p_attn, g_attn);
    cudaGetSymbolAddress((void**)&p_x2,   g_x2);
    cudaGetSymbolAddress((void**)&p_hid,  g_hid);
    cudaGetSymbolAddress((void**)&p_qkv_wt,  g_qkv_wt);
    cudaGetSymbolAddress((void**)&p_proj_wt, g_proj_wt);
    cudaGetSymbolAddress((void**)&p_w1t,  g_w1t);
    cudaGetSymbolAddress((void**)&p_w2t,  g_w2t);

    cudaFuncSetAttribute(tc_gemm<0>, cudaFuncAttributeMaxDynamicSharedMemorySize, GEMM_SMEM);
    cudaFuncSetAttribute(tc_gemm<1>, cudaFuncAttributeMaxDynamicSharedMemorySize, GEMM_SMEM);
    cudaFuncSetAttribute(tc_gemm<3>, cudaFuncAttributeMaxDynamicSharedMemorySize, GEMM_SMEM);
    cudaFuncSetAttribute(proj_ln2_kernel, cudaFuncAttributeMaxDynamicSharedMemorySize, PROJ_SMEM);

    transpose_all_kernel<<<432, dim3(32, 8)>>>(qkv_w, proj_w, mlp_w1, mlp_w2,
                                               p_qkv_wt, p_proj_wt, p_w1t, p_w2t);
    bias_precompute_kernel<<<HEADS, 576>>>(btab, rel_idx);

    gather_ln1_kernel<<<NTOK_TOTAL / 8, 256>>>(x, ln1_g, ln1_b);

    const int Mb = NTOK_TOTAL / 128;  // 1008
    tc_gemm<0><<<dim3(6, Mb), 256, GEMM_SMEM>>>(p_h, p_qkv_wt, qkv_b, nullptr, p_qkv, 576, 192);
    attn_kernel<<<NWIN * HEADS / 8, 256>>>();
    proj_ln2_kernel<<<NTOK_TOTAL / 64, 256, PROJ_SMEM>>>(p_attn, p_proj_wt, proj_b, x, ln2_g, ln2_b);
    tc_gemm<1><<<dim3(8, Mb), 256, GEMM_SMEM>>>(p_h, p_w1t, mlp_b1, nullptr, p_hid, 768, 192);
    tc_gemm<3><<<dim3(2, Mb), 256, GEMM_SMEM>>>(p_hid, p_w2t, mlp_b2, p_x2, out, 192, 768);
}